// round 1
// baseline (speedup 1.0000x reference)
#include <cuda_runtime.h>
#include <math.h>

#define SEQ 2048
#define DMODEL 1024
#define NHEAD 16
#define DK 64
#define BATCH 4
#define MROWS (BATCH * SEQ)   // 8192

// Scratch (device globals — no allocation allowed)
__device__ float g_q[BATCH * SEQ * DMODEL];
__device__ float g_k[BATCH * SEQ * DMODEL];
__device__ float g_v[BATCH * SEQ * DMODEL];
__device__ float g_attn[BATCH * SEQ * DMODEL];

// ---------------------------------------------------------------------------
// GEMM: Y[M,N] = X[M,K] @ W[N,K]^T + bias[N]
// Block tile 128x128, BK=16, 256 threads, 8x8 per-thread microtile.
// ---------------------------------------------------------------------------
#define BM 128
#define BN 128
#define BK 16
#define PAD 4

__global__ __launch_bounds__(256, 2)
void gemm_bias_kernel(const float* __restrict__ X, const float* __restrict__ W,
                      const float* __restrict__ bias, float* __restrict__ Y,
                      int M, int N, int K)
{
    __shared__ float As[BK][BM + PAD];
    __shared__ float Bs[BK][BN + PAD];

    const int tid = threadIdx.x;
    const int m0 = blockIdx.y * BM;
    const int n0 = blockIdx.x * BN;
    const int ty = tid >> 4;       // 0..15 -> rows ty*8..ty*8+7
    const int tx = tid & 15;       // 0..15 -> cols tx*8..tx*8+7

    const int lrow = tid >> 1;          // 0..127
    const int lk4  = (tid & 1) * 2;     // float4 group base: 0 or 2

    float acc[8][8];
#pragma unroll
    for (int i = 0; i < 8; i++)
#pragma unroll
        for (int j = 0; j < 8; j++) acc[i][j] = 0.0f;

    for (int k0 = 0; k0 < K; k0 += BK) {
        // Load A tile (transposed into As[k][m]) and B tile (Bs[k][n])
#pragma unroll
        for (int i = 0; i < 2; i++) {
            const int f4 = lk4 + i;            // 0..3
            const int kk = f4 * 4;
            float4 a = *(const float4*)&X[(size_t)(m0 + lrow) * K + k0 + kk];
            As[kk + 0][lrow] = a.x;
            As[kk + 1][lrow] = a.y;
            As[kk + 2][lrow] = a.z;
            As[kk + 3][lrow] = a.w;
            float4 b = *(const float4*)&W[(size_t)(n0 + lrow) * K + k0 + kk];
            Bs[kk + 0][lrow] = b.x;
            Bs[kk + 1][lrow] = b.y;
            Bs[kk + 2][lrow] = b.z;
            Bs[kk + 3][lrow] = b.w;
        }
        __syncthreads();

#pragma unroll
        for (int k = 0; k < BK; k++) {
            float a[8], b[8];
            *(float4*)&a[0] = *(const float4*)&As[k][ty * 8];
            *(float4*)&a[4] = *(const float4*)&As[k][ty * 8 + 4];
            *(float4*)&b[0] = *(const float4*)&Bs[k][tx * 8];
            *(float4*)&b[4] = *(const float4*)&Bs[k][tx * 8 + 4];
#pragma unroll
            for (int i = 0; i < 8; i++)
#pragma unroll
                for (int j = 0; j < 8; j++)
                    acc[i][j] += a[i] * b[j];
        }
        __syncthreads();
    }

    // Epilogue: add bias, store
#pragma unroll
    for (int i = 0; i < 8; i++) {
        const int m = m0 + ty * 8 + i;
#pragma unroll
        for (int j = 0; j < 8; j += 4) {
            const int n = n0 + tx * 8 + j;
            float4 bb = *(const float4*)&bias[n];
            float4 o;
            o.x = acc[i][j + 0] + bb.x;
            o.y = acc[i][j + 1] + bb.y;
            o.z = acc[i][j + 2] + bb.z;
            o.w = acc[i][j + 3] + bb.w;
            *(float4*)&Y[(size_t)m * N + n] = o;
        }
    }
}

// ---------------------------------------------------------------------------
// Flash attention (causal), fp32. One block = one (b, h, q-tile of 64).
// 256 threads; thread microtile 4x4. Online softmax.
// Q/K/V layout: [B, S, DMODEL] with head h at columns [h*64, h*64+64).
// ---------------------------------------------------------------------------
#define BQ 64
#define BKV 64
#define SPAD 68   // row stride of smem tiles (floats), 16B-aligned

__global__ __launch_bounds__(256, 2)
void flash_attn_kernel(const float* __restrict__ Q, const float* __restrict__ K,
                       const float* __restrict__ V, float* __restrict__ O)
{
    extern __shared__ float sm[];
    float* Qs = sm;                       // 64 x SPAD
    float* Ks = sm + BQ * SPAD;
    float* Vs = sm + 2 * BQ * SPAD;
    float* Ps = sm + 3 * BQ * SPAD;

    const int tid = threadIdx.x;
    const int ty = tid >> 4;   // 0..15 -> rows ty*4..+3
    const int tx = tid & 15;   // 0..15 -> cols tx*4..+3

    const int qt = blockIdx.x;
    const int h  = blockIdx.y;
    const int b  = blockIdx.z;

    const float* Qg = Q + (size_t)b * SEQ * DMODEL + (size_t)h * DK;
    const float* Kg = K + (size_t)b * SEQ * DMODEL + (size_t)h * DK;
    const float* Vg = V + (size_t)b * SEQ * DMODEL + (size_t)h * DK;
    float* Og       = O + (size_t)b * SEQ * DMODEL + (size_t)h * DK;

    // Load Q tile: 64 rows x 64 cols = 1024 float4
#pragma unroll
    for (int it = 0; it < 4; it++) {
        const int idx = tid + it * 256;   // 0..1023
        const int r  = idx >> 4;
        const int c4 = idx & 15;
        float4 qv = *(const float4*)&Qg[(size_t)(qt * BQ + r) * DMODEL + c4 * 4];
        *(float4*)&Qs[r * SPAD + c4 * 4] = qv;
    }

    float m_i[4], l_i[4], accv[4][4];
#pragma unroll
    for (int i = 0; i < 4; i++) {
        m_i[i] = -1e30f;
        l_i[i] = 0.0f;
#pragma unroll
        for (int j = 0; j < 4; j++) accv[i][j] = 0.0f;
    }

    const float scale = 0.125f;  // 1/sqrt(64)

    for (int kt = 0; kt <= qt; kt++) {
        __syncthreads();   // previous iteration done with Ks/Vs/Ps
        // Load K and V tiles
#pragma unroll
        for (int it = 0; it < 4; it++) {
            const int idx = tid + it * 256;
            const int r  = idx >> 4;
            const int c4 = idx & 15;
            const size_t goff = (size_t)(kt * BKV + r) * DMODEL + c4 * 4;
            *(float4*)&Ks[r * SPAD + c4 * 4] = *(const float4*)&Kg[goff];
            *(float4*)&Vs[r * SPAD + c4 * 4] = *(const float4*)&Vg[goff];
        }
        __syncthreads();

        // Scores: s[i][j] = sum_d Q[ty*4+i][d] * K[tx*4+j][d]
        float s[4][4];
#pragma unroll
        for (int i = 0; i < 4; i++)
#pragma unroll
            for (int j = 0; j < 4; j++) s[i][j] = 0.0f;

#pragma unroll
        for (int d4 = 0; d4 < 16; d4++) {
            float4 qv[4], kv[4];
#pragma unroll
            for (int i = 0; i < 4; i++)
                qv[i] = *(const float4*)&Qs[(ty * 4 + i) * SPAD + d4 * 4];
#pragma unroll
            for (int j = 0; j < 4; j++)
                kv[j] = *(const float4*)&Ks[(tx * 4 + j) * SPAD + d4 * 4];
#pragma unroll
            for (int i = 0; i < 4; i++)
#pragma unroll
                for (int j = 0; j < 4; j++)
                    s[i][j] += qv[i].x * kv[j].x + qv[i].y * kv[j].y
                             + qv[i].z * kv[j].z + qv[i].w * kv[j].w;
        }

        // Scale + causal mask (only diagonal tile needs masking)
        if (kt == qt) {
#pragma unroll
            for (int i = 0; i < 4; i++)
#pragma unroll
                for (int j = 0; j < 4; j++)
                    s[i][j] = (tx * 4 + j > ty * 4 + i) ? -1e30f : s[i][j] * scale;
        } else {
#pragma unroll
            for (int i = 0; i < 4; i++)
#pragma unroll
                for (int j = 0; j < 4; j++) s[i][j] *= scale;
        }

        // Row max across the 16 tx threads of this row group
        float rmax[4];
#pragma unroll
        for (int i = 0; i < 4; i++) {
            rmax[i] = fmaxf(fmaxf(s[i][0], s[i][1]), fmaxf(s[i][2], s[i][3]));
#pragma unroll
            for (int off = 8; off >= 1; off >>= 1)
                rmax[i] = fmaxf(rmax[i], __shfl_xor_sync(0xffffffffu, rmax[i], off));
        }

        float p[4][4], rsum[4], alpha[4];
#pragma unroll
        for (int i = 0; i < 4; i++) {
            const float mnew = fmaxf(m_i[i], rmax[i]);
            alpha[i] = expf(m_i[i] - mnew);
            m_i[i] = mnew;
            float rs = 0.0f;
#pragma unroll
            for (int j = 0; j < 4; j++) {
                p[i][j] = expf(s[i][j] - mnew);
                rs += p[i][j];
            }
            rsum[i] = rs;
#pragma unroll
            for (int off = 8; off >= 1; off >>= 1)
                rsum[i] += __shfl_xor_sync(0xffffffffu, rsum[i], off);
            l_i[i] = l_i[i] * alpha[i] + rsum[i];
#pragma unroll
            for (int j = 0; j < 4; j++) accv[i][j] *= alpha[i];
            // Write p to shared
            float4 pv4 = make_float4(p[i][0], p[i][1], p[i][2], p[i][3]);
            *(float4*)&Ps[(ty * 4 + i) * SPAD + tx * 4] = pv4;
        }
        __syncthreads();

        // PV: acc[i][c] += sum_j Ps[row_i][j] * Vs[j][tx*4 + c]
#pragma unroll
        for (int j4 = 0; j4 < 16; j4++) {
            float4 pv[4], vv[4];
#pragma unroll
            for (int i = 0; i < 4; i++)
                pv[i] = *(const float4*)&Ps[(ty * 4 + i) * SPAD + j4 * 4];
#pragma unroll
            for (int jj = 0; jj < 4; jj++)
                vv[jj] = *(const float4*)&Vs[(j4 * 4 + jj) * SPAD + tx * 4];
#pragma unroll
            for (int i = 0; i < 4; i++) {
                accv[i][0] += pv[i].x * vv[0].x + pv[i].y * vv[1].x + pv[i].z * vv[2].x + pv[i].w * vv[3].x;
                accv[i][1] += pv[i].x * vv[0].y + pv[i].y * vv[1].y + pv[i].z * vv[2].y + pv[i].w * vv[3].y;
                accv[i][2] += pv[i].x * vv[0].z + pv[i].y * vv[1].z + pv[i].z * vv[2].z + pv[i].w * vv[3].z;
                accv[i][3] += pv[i].x * vv[0].w + pv[i].y * vv[1].w + pv[i].z * vv[2].w + pv[i].w * vv[3].w;
            }
        }
    }

    // Epilogue: normalize and store
#pragma unroll
    for (int i = 0; i < 4; i++) {
        const float inv = 1.0f / l_i[i];
        float4 o;
        o.x = accv[i][0] * inv;
        o.y = accv[i][1] * inv;
        o.z = accv[i][2] * inv;
        o.w = accv[i][3] * inv;
        *(float4*)&Og[(size_t)(qt * BQ + ty * 4 + i) * DMODEL + tx * 4] = o;
    }
}

// ---------------------------------------------------------------------------
// Launch
// ---------------------------------------------------------------------------
extern "C" void kernel_launch(void* const* d_in, const int* in_sizes, int n_in,
                              void* d_out, int out_size)
{
    const float* query = (const float*)d_in[0];
    const float* key   = (const float*)d_in[1];
    const float* value = (const float*)d_in[2];
    const float* Wq = (const float*)d_in[3];
    const float* bq = (const float*)d_in[4];
    const float* Wk = (const float*)d_in[5];
    const float* bk = (const float*)d_in[6];
    const float* Wv = (const float*)d_in[7];
    const float* bv = (const float*)d_in[8];
    const float* Wo = (const float*)d_in[9];
    const float* bo = (const float*)d_in[10];
    float* out = (float*)d_out;

    float *q_s, *k_s, *v_s, *a_s;
    cudaGetSymbolAddress((void**)&q_s, g_q);
    cudaGetSymbolAddress((void**)&k_s, g_k);
    cudaGetSymbolAddress((void**)&v_s, g_v);
    cudaGetSymbolAddress((void**)&a_s, g_attn);

    const int smem_attn = 4 * BQ * SPAD * sizeof(float);  // 69,632 B
    cudaFuncSetAttribute(flash_attn_kernel,
                         cudaFuncAttributeMaxDynamicSharedMemorySize, smem_attn);

    dim3 gemm_grid(DMODEL / BN, MROWS / BM);   // (8, 64)
    gemm_bias_kernel<<<gemm_grid, 256>>>(query, Wq, bq, q_s, MROWS, DMODEL, DMODEL);
    gemm_bias_kernel<<<gemm_grid, 256>>>(key,   Wk, bk, k_s, MROWS, DMODEL, DMODEL);
    gemm_bias_kernel<<<gemm_grid, 256>>>(value, Wv, bv, v_s, MROWS, DMODEL, DMODEL);

    dim3 attn_grid(SEQ / BQ, NHEAD, BATCH);    // (32, 16, 4)
    flash_attn_kernel<<<attn_grid, 256, smem_attn>>>(q_s, k_s, v_s, a_s);

    gemm_bias_kernel<<<gemm_grid, 256>>>(a_s, Wo, bo, out, MROWS, DMODEL, DMODEL);
}

// round 5
// speedup vs baseline: 1.4131x; 1.4131x over previous
#include <cuda_runtime.h>
#include <cuda_bf16.h>
#include <math.h>
#include <stdint.h>

#define SEQ 2048
#define DMODEL 1024
#define NHEAD 16
#define DK 64
#define BATCH 4
#define MROWS (BATCH * SEQ)   // 8192

// ---------------------------------------------------------------------------
// Scratch (device globals — no allocation allowed)
// ---------------------------------------------------------------------------
__device__ float g_q[MROWS * DMODEL];
__device__ float g_k[MROWS * DMODEL];
__device__ float g_v[MROWS * DMODEL];
__device__ float g_attn[MROWS * DMODEL];
__device__ __nv_bfloat16 g_ah[MROWS * DMODEL];
__device__ __nv_bfloat16 g_al[MROWS * DMODEL];
__device__ __nv_bfloat16 g_wh[DMODEL * DMODEL];
__device__ __nv_bfloat16 g_wl[DMODEL * DMODEL];

// ---------------------------------------------------------------------------
// fp32 -> (bf16 hi, bf16 lo) split kernel
// ---------------------------------------------------------------------------
__global__ void cvt_split_kernel(const float* __restrict__ x,
                                 __nv_bfloat16* __restrict__ hi,
                                 __nv_bfloat16* __restrict__ lo, int n4)
{
    int i = blockIdx.x * blockDim.x + threadIdx.x;
    if (i >= n4) return;
    float4 v = ((const float4*)x)[i];
    __nv_bfloat16 h0 = __float2bfloat16(v.x);
    __nv_bfloat16 h1 = __float2bfloat16(v.y);
    __nv_bfloat16 h2 = __float2bfloat16(v.z);
    __nv_bfloat16 h3 = __float2bfloat16(v.w);
    __nv_bfloat16 l0 = __float2bfloat16(v.x - __bfloat162float(h0));
    __nv_bfloat16 l1 = __float2bfloat16(v.y - __bfloat162float(h1));
    __nv_bfloat16 l2 = __float2bfloat16(v.z - __bfloat162float(h2));
    __nv_bfloat16 l3 = __float2bfloat16(v.w - __bfloat162float(h3));
    __nv_bfloat162 hA = __halves2bfloat162(h0, h1);
    __nv_bfloat162 hB = __halves2bfloat162(h2, h3);
    __nv_bfloat162 lA = __halves2bfloat162(l0, l1);
    __nv_bfloat162 lB = __halves2bfloat162(l2, l3);
    uint2 hu = make_uint2(*(uint32_t*)&hA, *(uint32_t*)&hB);
    uint2 lu = make_uint2(*(uint32_t*)&lA, *(uint32_t*)&lB);
    *(uint2*)(hi + (size_t)i * 4) = hu;
    *(uint2*)(lo + (size_t)i * 4) = lu;
}

// ---------------------------------------------------------------------------
// mma.sync bf16 GEMM (3-term emulation): Y[M,N] = X[M,K] @ W[N,K]^T + bias
// CTA 128x128, BK=32, 8 warps (2x4), warp tile 64x32.
// SMEM row stride 40 bf16 (80 B) -> conflict-free fragment LDS.
// cp.async double-buffered.
// ---------------------------------------------------------------------------
#define BKC 32
#define NCHUNKS (DMODEL / BKC)          // 32
#define ROW_STRIDE 40                   // bf16 units (80 B)
#define TILE_U (128 * ROW_STRIDE)       // bf16 units per tile (5120)
#define STAGE_U (4 * TILE_U)            // 4 tiles: Ah, Al, Bh, Bl
#define SMEM_GEMM_BYTES (2 * STAGE_U * 2)  // 81920

#define CP_ASYNC16(dst, src) \
    asm volatile("cp.async.cg.shared.global [%0], [%1], 16;" :: "r"(dst), "l"(src))
#define CP_COMMIT() asm volatile("cp.async.commit_group;")
#define CP_WAIT1() asm volatile("cp.async.wait_group 1;")
#define CP_WAIT0() asm volatile("cp.async.wait_group 0;")

#define MMA_BF16(c, a, b) \
    asm volatile("mma.sync.aligned.m16n8k16.row.col.f32.bf16.bf16.f32 " \
                 "{%0,%1,%2,%3}, {%4,%5,%6,%7}, {%8,%9}, {%0,%1,%2,%3};" \
                 : "+f"((c)[0]), "+f"((c)[1]), "+f"((c)[2]), "+f"((c)[3]) \
                 : "r"((a)[0]), "r"((a)[1]), "r"((a)[2]), "r"((a)[3]), \
                   "r"((b)[0]), "r"((b)[1]))

__device__ __forceinline__ uint32_t smem_u32(const void* p) {
    uint32_t a;
    asm("{ .reg .u64 t; cvta.to.shared.u64 t, %1; cvt.u32.u64 %0, t; }"
        : "=r"(a) : "l"(p));
    return a;
}

__global__ __launch_bounds__(256, 2)
void gemm_mma_kernel(const __nv_bfloat16* __restrict__ Ah,
                     const __nv_bfloat16* __restrict__ Al,
                     const __nv_bfloat16* __restrict__ Bh,
                     const __nv_bfloat16* __restrict__ Bl,
                     const float* __restrict__ bias,
                     float* __restrict__ Y)
{
    extern __shared__ __align__(16) __nv_bfloat16 smb[];
    const uint32_t smem_base = smem_u32(smb);

    const int tid  = threadIdx.x;
    const int lane = tid & 31;
    const int w    = tid >> 5;
    const int wm   = w >> 2;            // 0..1
    const int wn   = w & 3;             // 0..3
    const int gid  = lane >> 2;         // 0..7
    const int tig  = lane & 3;          // 0..3
    const int m0 = blockIdx.y * 128;
    const int n0 = blockIdx.x * 128;

    float acc[4][4][4];
#pragma unroll
    for (int i = 0; i < 4; i++)
#pragma unroll
        for (int j = 0; j < 4; j++)
#pragma unroll
            for (int r = 0; r < 4; r++) acc[i][j][r] = 0.0f;

    // ---- async loader: 2048 16B-chunks per stage / 256 threads = 8 each ----
    // it 0..7 -> tile = it>>1, within = (it&1)*256+tid, row = within>>2, ch = within&3
    auto load_stage = [&](int s, int kc) {
#pragma unroll
        for (int it = 0; it < 8; it++) {
            const int tile   = it >> 1;
            const int within = (it & 1) * 256 + tid;
            const int row    = within >> 2;
            const int ch     = within & 3;
            const __nv_bfloat16* src =
                (tile == 0) ? Ah : (tile == 1) ? Al : (tile == 2) ? Bh : Bl;
            const int gbase = ((tile < 2) ? m0 : n0) + row;
            const __nv_bfloat16* gp = src + (size_t)gbase * DMODEL + kc + ch * 8;
            const uint32_t daddr = smem_base +
                (s * STAGE_U + tile * TILE_U + row * ROW_STRIDE) * 2 + ch * 16;
            CP_ASYNC16(daddr, gp);
        }
        CP_COMMIT();
    };

    load_stage(0, 0);
    load_stage(1, BKC);

    // Precomputed fragment base indices (bf16 units) within a tile
    const int aRow0 = wm * 64 + gid;        // + i*16 (+8)
    const int bRow0 = wn * 32 + gid;        // + j*8

    for (int c = 0; c < NCHUNKS; c++) {
        if (c < NCHUNKS - 2) CP_WAIT1(); else CP_WAIT0();
        __syncthreads();

        const __nv_bfloat16* st = smb + (c & 1) * STAGE_U;
        const __nv_bfloat16* tAh = st;
        const __nv_bfloat16* tAl = st + TILE_U;
        const __nv_bfloat16* tBh = st + 2 * TILE_U;
        const __nv_bfloat16* tBl = st + 3 * TILE_U;

#pragma unroll
        for (int kk = 0; kk < BKC; kk += 16) {
            uint32_t ah[4][4], al[4][4], bh[4][2], bl[4][2];
#pragma unroll
            for (int i = 0; i < 4; i++) {
                const int r = aRow0 + i * 16;
                const int k0i = kk + 2 * tig;
                ah[i][0] = *(const uint32_t*)&tAh[r * ROW_STRIDE + k0i];
                ah[i][1] = *(const uint32_t*)&tAh[(r + 8) * ROW_STRIDE + k0i];
                ah[i][2] = *(const uint32_t*)&tAh[r * ROW_STRIDE + k0i + 8];
                ah[i][3] = *(const uint32_t*)&tAh[(r + 8) * ROW_STRIDE + k0i + 8];
                al[i][0] = *(const uint32_t*)&tAl[r * ROW_STRIDE + k0i];
                al[i][1] = *(const uint32_t*)&tAl[(r + 8) * ROW_STRIDE + k0i];
                al[i][2] = *(const uint32_t*)&tAl[r * ROW_STRIDE + k0i + 8];
                al[i][3] = *(const uint32_t*)&tAl[(r + 8) * ROW_STRIDE + k0i + 8];
            }
#pragma unroll
            for (int j = 0; j < 4; j++) {
                const int r = bRow0 + j * 8;
                const int k0i = kk + 2 * tig;
                bh[j][0] = *(const uint32_t*)&tBh[r * ROW_STRIDE + k0i];
                bh[j][1] = *(const uint32_t*)&tBh[r * ROW_STRIDE + k0i + 8];
                bl[j][0] = *(const uint32_t*)&tBl[r * ROW_STRIDE + k0i];
                bl[j][1] = *(const uint32_t*)&tBl[r * ROW_STRIDE + k0i + 8];
            }
#pragma unroll
            for (int i = 0; i < 4; i++)
#pragma unroll
                for (int j = 0; j < 4; j++) {
                    MMA_BF16(acc[i][j], ah[i], bh[j]);
                    MMA_BF16(acc[i][j], ah[i], bl[j]);
                    MMA_BF16(acc[i][j], al[i], bh[j]);
                }
        }
        __syncthreads();
        if (c + 2 < NCHUNKS) load_stage(c & 1, (c + 2) * BKC);
    }

    // ---- epilogue: direct register -> gmem float2 stores, + bias ----
#pragma unroll
    for (int i = 0; i < 4; i++) {
        const int r0 = m0 + wm * 64 + i * 16 + gid;
#pragma unroll
        for (int j = 0; j < 4; j++) {
            const int col = n0 + wn * 32 + j * 8 + 2 * tig;
            const float bx = bias[col];
            const float by = bias[col + 1];
            float2 v0 = make_float2(acc[i][j][0] + bx, acc[i][j][1] + by);
            float2 v1 = make_float2(acc[i][j][2] + bx, acc[i][j][3] + by);
            *(float2*)&Y[(size_t)r0 * DMODEL + col] = v0;
            *(float2*)&Y[(size_t)(r0 + 8) * DMODEL + col] = v1;
        }
    }
}

// ---------------------------------------------------------------------------
// Flash attention (causal), fp32 — unchanged.
// ---------------------------------------------------------------------------
#define BQ 64
#define BKV 64
#define SPAD 68

__global__ __launch_bounds__(256, 2)
void flash_attn_kernel(const float* __restrict__ Q, const float* __restrict__ K,
                       const float* __restrict__ V, float* __restrict__ O)
{
    extern __shared__ float sm[];
    float* Qs = sm;
    float* Ks = sm + BQ * SPAD;
    float* Vs = sm + 2 * BQ * SPAD;
    float* Ps = sm + 3 * BQ * SPAD;

    const int tid = threadIdx.x;
    const int ty = tid >> 4;
    const int tx = tid & 15;

    const int qt = blockIdx.x;
    const int h  = blockIdx.y;
    const int b  = blockIdx.z;

    const float* Qg = Q + (size_t)b * SEQ * DMODEL + (size_t)h * DK;
    const float* Kg = K + (size_t)b * SEQ * DMODEL + (size_t)h * DK;
    const float* Vg = V + (size_t)b * SEQ * DMODEL + (size_t)h * DK;
    float* Og       = O + (size_t)b * SEQ * DMODEL + (size_t)h * DK;

#pragma unroll
    for (int it = 0; it < 4; it++) {
        const int idx = tid + it * 256;
        const int r  = idx >> 4;
        const int c4 = idx & 15;
        float4 qv = *(const float4*)&Qg[(size_t)(qt * BQ + r) * DMODEL + c4 * 4];
        *(float4*)&Qs[r * SPAD + c4 * 4] = qv;
    }

    float m_i[4], l_i[4], accv[4][4];
#pragma unroll
    for (int i = 0; i < 4; i++) {
        m_i[i] = -1e30f;
        l_i[i] = 0.0f;
#pragma unroll
        for (int j = 0; j < 4; j++) accv[i][j] = 0.0f;
    }

    const float scale = 0.125f;

    for (int kt = 0; kt <= qt; kt++) {
        __syncthreads();
#pragma unroll
        for (int it = 0; it < 4; it++) {
            const int idx = tid + it * 256;
            const int r  = idx >> 4;
            const int c4 = idx & 15;
            const size_t goff = (size_t)(kt * BKV + r) * DMODEL + c4 * 4;
            *(float4*)&Ks[r * SPAD + c4 * 4] = *(const float4*)&Kg[goff];
            *(float4*)&Vs[r * SPAD + c4 * 4] = *(const float4*)&Vg[goff];
        }
        __syncthreads();

        float s[4][4];
#pragma unroll
        for (int i = 0; i < 4; i++)
#pragma unroll
            for (int j = 0; j < 4; j++) s[i][j] = 0.0f;

#pragma unroll
        for (int d4 = 0; d4 < 16; d4++) {
            float4 qv[4], kv[4];
#pragma unroll
            for (int i = 0; i < 4; i++)
                qv[i] = *(const float4*)&Qs[(ty * 4 + i) * SPAD + d4 * 4];
#pragma unroll
            for (int j = 0; j < 4; j++)
                kv[j] = *(const float4*)&Ks[(tx * 4 + j) * SPAD + d4 * 4];
#pragma unroll
            for (int i = 0; i < 4; i++)
#pragma unroll
                for (int j = 0; j < 4; j++)
                    s[i][j] += qv[i].x * kv[j].x + qv[i].y * kv[j].y
                             + qv[i].z * kv[j].z + qv[i].w * kv[j].w;
        }

        if (kt == qt) {
#pragma unroll
            for (int i = 0; i < 4; i++)
#pragma unroll
                for (int j = 0; j < 4; j++)
                    s[i][j] = (tx * 4 + j > ty * 4 + i) ? -1e30f : s[i][j] * scale;
        } else {
#pragma unroll
            for (int i = 0; i < 4; i++)
#pragma unroll
                for (int j = 0; j < 4; j++) s[i][j] *= scale;
        }

        float rmax[4];
#pragma unroll
        for (int i = 0; i < 4; i++) {
            rmax[i] = fmaxf(fmaxf(s[i][0], s[i][1]), fmaxf(s[i][2], s[i][3]));
#pragma unroll
            for (int off = 8; off >= 1; off >>= 1)
                rmax[i] = fmaxf(rmax[i], __shfl_xor_sync(0xffffffffu, rmax[i], off));
        }

        float p[4][4], rsum[4], alpha[4];
#pragma unroll
        for (int i = 0; i < 4; i++) {
            const float mnew = fmaxf(m_i[i], rmax[i]);
            alpha[i] = expf(m_i[i] - mnew);
            m_i[i] = mnew;
            float rs = 0.0f;
#pragma unroll
            for (int j = 0; j < 4; j++) {
                p[i][j] = expf(s[i][j] - mnew);
                rs += p[i][j];
            }
            rsum[i] = rs;
#pragma unroll
            for (int off = 8; off >= 1; off >>= 1)
                rsum[i] += __shfl_xor_sync(0xffffffffu, rsum[i], off);
            l_i[i] = l_i[i] * alpha[i] + rsum[i];
#pragma unroll
            for (int j = 0; j < 4; j++) accv[i][j] *= alpha[i];
            float4 pv4 = make_float4(p[i][0], p[i][1], p[i][2], p[i][3]);
            *(float4*)&Ps[(ty * 4 + i) * SPAD + tx * 4] = pv4;
        }
        __syncthreads();

#pragma unroll
        for (int j4 = 0; j4 < 16; j4++) {
            float4 pv[4], vv[4];
#pragma unroll
            for (int i = 0; i < 4; i++)
                pv[i] = *(const float4*)&Ps[(ty * 4 + i) * SPAD + j4 * 4];
#pragma unroll
            for (int jj = 0; jj < 4; jj++)
                vv[jj] = *(const float4*)&Vs[(j4 * 4 + jj) * SPAD + tx * 4];
#pragma unroll
            for (int i = 0; i < 4; i++) {
                accv[i][0] += pv[i].x * vv[0].x + pv[i].y * vv[1].x + pv[i].z * vv[2].x + pv[i].w * vv[3].x;
                accv[i][1] += pv[i].x * vv[0].y + pv[i].y * vv[1].y + pv[i].z * vv[2].y + pv[i].w * vv[3].y;
                accv[i][2] += pv[i].x * vv[0].z + pv[i].y * vv[1].z + pv[i].z * vv[2].z + pv[i].w * vv[3].z;
                accv[i][3] += pv[i].x * vv[0].w + pv[i].y * vv[1].w + pv[i].z * vv[2].w + pv[i].w * vv[3].w;
            }
        }
    }

#pragma unroll
    for (int i = 0; i < 4; i++) {
        const float inv = 1.0f / l_i[i];
        float4 o;
        o.x = accv[i][0] * inv;
        o.y = accv[i][1] * inv;
        o.z = accv[i][2] * inv;
        o.w = accv[i][3] * inv;
        *(float4*)&Og[(size_t)(qt * BQ + ty * 4 + i) * DMODEL + tx * 4] = o;
    }
}

// ---------------------------------------------------------------------------
// Launch
// ---------------------------------------------------------------------------
extern "C" void kernel_launch(void* const* d_in, const int* in_sizes, int n_in,
                              void* d_out, int out_size)
{
    const float* query = (const float*)d_in[0];
    const float* key   = (const float*)d_in[1];
    const float* value = (const float*)d_in[2];
    const float* Wq = (const float*)d_in[3];
    const float* bq = (const float*)d_in[4];
    const float* Wk = (const float*)d_in[5];
    const float* bk = (const float*)d_in[6];
    const float* Wv = (const float*)d_in[7];
    const float* bv = (const float*)d_in[8];
    const float* Wo = (const float*)d_in[9];
    const float* bo = (const float*)d_in[10];
    float* out = (float*)d_out;

    float *q_s, *k_s, *v_s, *a_s;
    __nv_bfloat16 *ah, *al, *wh, *wl;
    cudaGetSymbolAddress((void**)&q_s, g_q);
    cudaGetSymbolAddress((void**)&k_s, g_k);
    cudaGetSymbolAddress((void**)&v_s, g_v);
    cudaGetSymbolAddress((void**)&a_s, g_attn);
    cudaGetSymbolAddress((void**)&ah, g_ah);
    cudaGetSymbolAddress((void**)&al, g_al);
    cudaGetSymbolAddress((void**)&wh, g_wh);
    cudaGetSymbolAddress((void**)&wl, g_wl);

    cudaFuncSetAttribute(gemm_mma_kernel,
                         cudaFuncAttributeMaxDynamicSharedMemorySize, SMEM_GEMM_BYTES);
    const int smem_attn = 4 * BQ * SPAD * sizeof(float);
    cudaFuncSetAttribute(flash_attn_kernel,
                         cudaFuncAttributeMaxDynamicSharedMemorySize, smem_attn);

    const dim3 gg(DMODEL / 128, MROWS / 128);   // (8, 64)
    const int nact4 = MROWS * DMODEL / 4;
    const int nw4 = DMODEL * DMODEL / 4;

    // Q projection
    cvt_split_kernel<<<nact4 / 256, 256>>>(query, ah, al, nact4);
    cvt_split_kernel<<<nw4 / 256, 256>>>(Wq, wh, wl, nw4);
    gemm_mma_kernel<<<gg, 256, SMEM_GEMM_BYTES>>>(ah, al, wh, wl, bq, q_s);
    // K projection
    cvt_split_kernel<<<nact4 / 256, 256>>>(key, ah, al, nact4);
    cvt_split_kernel<<<nw4 / 256, 256>>>(Wk, wh, wl, nw4);
    gemm_mma_kernel<<<gg, 256, SMEM_GEMM_BYTES>>>(ah, al, wh, wl, bk, k_s);
    // V projection
    cvt_split_kernel<<<nact4 / 256, 256>>>(value, ah, al, nact4);
    cvt_split_kernel<<<nw4 / 256, 256>>>(Wv, wh, wl, nw4);
    gemm_mma_kernel<<<gg, 256, SMEM_GEMM_BYTES>>>(ah, al, wh, wl, bv, v_s);

    // Attention
    const dim3 ag(SEQ / BQ, NHEAD, BATCH);
    flash_attn_kernel<<<ag, 256, smem_attn>>>(q_s, k_s, v_s, a_s);

    // Output projection
    cvt_split_kernel<<<nact4 / 256, 256>>>(a_s, ah, al, nact4);
    cvt_split_kernel<<<nw4 / 256, 256>>>(Wo, wh, wl, nw4);
    gemm_mma_kernel<<<gg, 256, SMEM_GEMM_BYTES>>>(ah, al, wh, wl, bo, out);
}

// round 6
// speedup vs baseline: 3.2060x; 2.2688x over previous
#include <cuda_runtime.h>
#include <cuda_bf16.h>
#include <math.h>
#include <stdint.h>

#define SEQ 2048
#define DMODEL 1024
#define NHEAD 16
#define DK 64
#define BATCH 4
#define MROWS (BATCH * SEQ)   // 8192

// ---------------------------------------------------------------------------
// Scratch (device globals — no allocation allowed)
// ---------------------------------------------------------------------------
__device__ float g_q[MROWS * DMODEL];
__device__ float g_k[MROWS * DMODEL];
__device__ float g_v[MROWS * DMODEL];
__device__ float g_attn[MROWS * DMODEL];
__device__ __nv_bfloat16 g_ah[MROWS * DMODEL];
__device__ __nv_bfloat16 g_al[MROWS * DMODEL];
__device__ __nv_bfloat16 g_wh[DMODEL * DMODEL];
__device__ __nv_bfloat16 g_wl[DMODEL * DMODEL];
// attention operands
__device__ __nv_bfloat16 g_qh[MROWS * DMODEL];
__device__ __nv_bfloat16 g_ql[MROWS * DMODEL];
__device__ __nv_bfloat16 g_kh[MROWS * DMODEL];
__device__ __nv_bfloat16 g_kl[MROWS * DMODEL];
__device__ __nv_bfloat16 g_vth[MROWS * DMODEL];  // [bh][d][s]
__device__ __nv_bfloat16 g_vtl[MROWS * DMODEL];

// ---------------------------------------------------------------------------
// Common asm helpers
// ---------------------------------------------------------------------------
__device__ __forceinline__ uint32_t smem_u32(const void* p) {
    uint32_t a;
    asm("{ .reg .u64 t; cvta.to.shared.u64 t, %1; cvt.u32.u64 %0, t; }"
        : "=r"(a) : "l"(p));
    return a;
}
#define CP_ASYNC16(dst, src) \
    asm volatile("cp.async.cg.shared.global [%0], [%1], 16;" :: "r"(dst), "l"(src))
#define CP_COMMIT() asm volatile("cp.async.commit_group;")
#define CP_WAIT1() asm volatile("cp.async.wait_group 1;")
#define CP_WAIT0() asm volatile("cp.async.wait_group 0;")
#define MMA_BF16(c, a, b) \
    asm volatile("mma.sync.aligned.m16n8k16.row.col.f32.bf16.bf16.f32 " \
                 "{%0,%1,%2,%3}, {%4,%5,%6,%7}, {%8,%9}, {%0,%1,%2,%3};" \
                 : "+f"((c)[0]), "+f"((c)[1]), "+f"((c)[2]), "+f"((c)[3]) \
                 : "r"((a)[0]), "r"((a)[1]), "r"((a)[2]), "r"((a)[3]), \
                   "r"((b)[0]), "r"((b)[1]))
#define LDM_X4(r0, r1, r2, r3, addr) \
    asm volatile("ldmatrix.sync.aligned.m8n8.x4.shared.b16 {%0,%1,%2,%3}, [%4];" \
                 : "=r"(r0), "=r"(r1), "=r"(r2), "=r"(r3) : "r"(addr))

__device__ __forceinline__ uint32_t pack_bf16(float a, float b) {
    __nv_bfloat162 t = __floats2bfloat162_rn(a, b);
    return *(uint32_t*)&t;
}
__device__ __forceinline__ uint32_t pack_lo(float a, float b, uint32_t hpack) {
    __nv_bfloat162 h = *(__nv_bfloat162*)&hpack;
    return pack_bf16(a - __bfloat162float(h.x), b - __bfloat162float(h.y));
}

// ---------------------------------------------------------------------------
// fp32 -> (bf16 hi, bf16 lo) split kernel, with scale
// ---------------------------------------------------------------------------
__global__ void cvt_split_kernel(const float* __restrict__ x,
                                 __nv_bfloat16* __restrict__ hi,
                                 __nv_bfloat16* __restrict__ lo,
                                 float sc, int n4)
{
    int i = blockIdx.x * blockDim.x + threadIdx.x;
    if (i >= n4) return;
    float4 v = ((const float4*)x)[i];
    v.x *= sc; v.y *= sc; v.z *= sc; v.w *= sc;
    __nv_bfloat16 h0 = __float2bfloat16(v.x);
    __nv_bfloat16 h1 = __float2bfloat16(v.y);
    __nv_bfloat16 h2 = __float2bfloat16(v.z);
    __nv_bfloat16 h3 = __float2bfloat16(v.w);
    __nv_bfloat16 l0 = __float2bfloat16(v.x - __bfloat162float(h0));
    __nv_bfloat16 l1 = __float2bfloat16(v.y - __bfloat162float(h1));
    __nv_bfloat16 l2 = __float2bfloat16(v.z - __bfloat162float(h2));
    __nv_bfloat16 l3 = __float2bfloat16(v.w - __bfloat162float(h3));
    __nv_bfloat162 hA = __halves2bfloat162(h0, h1);
    __nv_bfloat162 hB = __halves2bfloat162(h2, h3);
    __nv_bfloat162 lA = __halves2bfloat162(l0, l1);
    __nv_bfloat162 lB = __halves2bfloat162(l2, l3);
    uint2 hu = make_uint2(*(uint32_t*)&hA, *(uint32_t*)&hB);
    uint2 lu = make_uint2(*(uint32_t*)&lA, *(uint32_t*)&lB);
    *(uint2*)(hi + (size_t)i * 4) = hu;
    *(uint2*)(lo + (size_t)i * 4) = lu;
}

// ---------------------------------------------------------------------------
// V transpose + split: [b][s][h*64+d] fp32 -> [bh][d][s] bf16 hi/lo
// ---------------------------------------------------------------------------
__global__ void vtrans_split_kernel(const float* __restrict__ v,
                                    __nv_bfloat16* __restrict__ vth,
                                    __nv_bfloat16* __restrict__ vtl)
{
    __shared__ float t[32][33];
    const int c0 = blockIdx.x * 32;   // dmodel col tile
    const int r0 = blockIdx.y * 32;   // row (b*s) tile
    const int tx = threadIdx.x, ty = threadIdx.y;
#pragma unroll
    for (int i = 0; i < 4; i++) {
        const int row = r0 + ty + i * 8;
        t[ty + i * 8][tx] = v[(size_t)row * DMODEL + c0 + tx];
    }
    __syncthreads();
#pragma unroll
    for (int i = 0; i < 4; i++) {
        const int col = c0 + ty + i * 8;
        const int srow = r0 + tx;
        const int b = srow >> 11, s = srow & 2047;
        const int h = col >> 6, d = col & 63;
        float x = t[tx][ty + i * 8];
        __nv_bfloat16 hi = __float2bfloat16(x);
        __nv_bfloat16 lo = __float2bfloat16(x - __bfloat162float(hi));
        size_t o = ((size_t)(b * NHEAD + h) * DK + d) * SEQ + s;
        vth[o] = hi;
        vtl[o] = lo;
    }
}

// ---------------------------------------------------------------------------
// mma.sync bf16 GEMM (3-term emulation) — unchanged from R4
// ---------------------------------------------------------------------------
#define BKC 32
#define NCHUNKS (DMODEL / BKC)
#define ROW_STRIDE 40
#define TILE_U (128 * ROW_STRIDE)
#define STAGE_U (4 * TILE_U)
#define SMEM_GEMM_BYTES (2 * STAGE_U * 2)

__global__ __launch_bounds__(256, 2)
void gemm_mma_kernel(const __nv_bfloat16* __restrict__ Ah,
                     const __nv_bfloat16* __restrict__ Al,
                     const __nv_bfloat16* __restrict__ Bh,
                     const __nv_bfloat16* __restrict__ Bl,
                     const float* __restrict__ bias,
                     float* __restrict__ Y)
{
    extern __shared__ __align__(16) __nv_bfloat16 smb[];
    const uint32_t smem_base = smem_u32(smb);

    const int tid  = threadIdx.x;
    const int lane = tid & 31;
    const int w    = tid >> 5;
    const int wm   = w >> 2;
    const int wn   = w & 3;
    const int gid  = lane >> 2;
    const int tig  = lane & 3;
    const int m0 = blockIdx.y * 128;
    const int n0 = blockIdx.x * 128;

    float acc[4][4][4];
#pragma unroll
    for (int i = 0; i < 4; i++)
#pragma unroll
        for (int j = 0; j < 4; j++)
#pragma unroll
            for (int r = 0; r < 4; r++) acc[i][j][r] = 0.0f;

    auto load_stage = [&](int s, int kc) {
#pragma unroll
        for (int it = 0; it < 8; it++) {
            const int tile   = it >> 1;
            const int within = (it & 1) * 256 + tid;
            const int row    = within >> 2;
            const int ch     = within & 3;
            const __nv_bfloat16* src =
                (tile == 0) ? Ah : (tile == 1) ? Al : (tile == 2) ? Bh : Bl;
            const int gbase = ((tile < 2) ? m0 : n0) + row;
            const __nv_bfloat16* gp = src + (size_t)gbase * DMODEL + kc + ch * 8;
            const uint32_t daddr = smem_base +
                (s * STAGE_U + tile * TILE_U + row * ROW_STRIDE) * 2 + ch * 16;
            CP_ASYNC16(daddr, gp);
        }
        CP_COMMIT();
    };

    load_stage(0, 0);
    load_stage(1, BKC);

    const int aRow0 = wm * 64 + gid;
    const int bRow0 = wn * 32 + gid;

    for (int c = 0; c < NCHUNKS; c++) {
        if (c < NCHUNKS - 2) CP_WAIT1(); else CP_WAIT0();
        __syncthreads();

        const __nv_bfloat16* st = smb + (c & 1) * STAGE_U;
        const __nv_bfloat16* tAh = st;
        const __nv_bfloat16* tAl = st + TILE_U;
        const __nv_bfloat16* tBh = st + 2 * TILE_U;
        const __nv_bfloat16* tBl = st + 3 * TILE_U;

#pragma unroll
        for (int kk = 0; kk < BKC; kk += 16) {
            uint32_t ah[4][4], al[4][4], bh[4][2], bl[4][2];
#pragma unroll
            for (int i = 0; i < 4; i++) {
                const int r = aRow0 + i * 16;
                const int k0i = kk + 2 * tig;
                ah[i][0] = *(const uint32_t*)&tAh[r * ROW_STRIDE + k0i];
                ah[i][1] = *(const uint32_t*)&tAh[(r + 8) * ROW_STRIDE + k0i];
                ah[i][2] = *(const uint32_t*)&tAh[r * ROW_STRIDE + k0i + 8];
                ah[i][3] = *(const uint32_t*)&tAh[(r + 8) * ROW_STRIDE + k0i + 8];
                al[i][0] = *(const uint32_t*)&tAl[r * ROW_STRIDE + k0i];
                al[i][1] = *(const uint32_t*)&tAl[(r + 8) * ROW_STRIDE + k0i];
                al[i][2] = *(const uint32_t*)&tAl[r * ROW_STRIDE + k0i + 8];
                al[i][3] = *(const uint32_t*)&tAl[(r + 8) * ROW_STRIDE + k0i + 8];
            }
#pragma unroll
            for (int j = 0; j < 4; j++) {
                const int r = bRow0 + j * 8;
                const int k0i = kk + 2 * tig;
                bh[j][0] = *(const uint32_t*)&tBh[r * ROW_STRIDE + k0i];
                bh[j][1] = *(const uint32_t*)&tBh[r * ROW_STRIDE + k0i + 8];
                bl[j][0] = *(const uint32_t*)&tBl[r * ROW_STRIDE + k0i];
                bl[j][1] = *(const uint32_t*)&tBl[r * ROW_STRIDE + k0i + 8];
            }
#pragma unroll
            for (int i = 0; i < 4; i++)
#pragma unroll
                for (int j = 0; j < 4; j++) {
                    MMA_BF16(acc[i][j], ah[i], bh[j]);
                    MMA_BF16(acc[i][j], ah[i], bl[j]);
                    MMA_BF16(acc[i][j], al[i], bh[j]);
                }
        }
        __syncthreads();
        if (c + 2 < NCHUNKS) load_stage(c & 1, (c + 2) * BKC);
    }

#pragma unroll
    for (int i = 0; i < 4; i++) {
        const int r0 = m0 + wm * 64 + i * 16 + gid;
#pragma unroll
        for (int j = 0; j < 4; j++) {
            const int col = n0 + wn * 32 + j * 8 + 2 * tig;
            const float bx = bias[col];
            const float by = bias[col + 1];
            float2 v0 = make_float2(acc[i][j][0] + bx, acc[i][j][1] + by);
            float2 v1 = make_float2(acc[i][j][2] + bx, acc[i][j][3] + by);
            *(float2*)&Y[(size_t)r0 * DMODEL + col] = v0;
            *(float2*)&Y[(size_t)(r0 + 8) * DMODEL + col] = v1;
        }
    }
}

// ---------------------------------------------------------------------------
// Tensor-core flash attention (causal), bf16 mma + 3-term emulation.
// Block = (b, h, 64-row q tile); 128 threads (4 warps), warp = 16 q rows.
// SMEM (bf16 units, stride 72): Qh[0], Ql[4608], stages at 9216 + st*18432,
//   each stage: Kh(0) Kl(4608) Vth(9216) Vtl(13824).  Total 92160 B.
// ---------------------------------------------------------------------------
#define FA_STRIDE 72
#define FA_TILE_U (64 * FA_STRIDE)              // 4608
#define FA_STAGE_U (4 * FA_TILE_U)              // 18432
#define FA_SMEM_BYTES ((2 * FA_TILE_U + 2 * FA_STAGE_U) * 2)  // 92160

__global__ __launch_bounds__(128, 2)
void flash_mma_kernel(const __nv_bfloat16* __restrict__ Qh,
                      const __nv_bfloat16* __restrict__ Ql,
                      const __nv_bfloat16* __restrict__ Kh,
                      const __nv_bfloat16* __restrict__ Kl,
                      const __nv_bfloat16* __restrict__ Vth,
                      const __nv_bfloat16* __restrict__ Vtl,
                      float* __restrict__ O)
{
    extern __shared__ __align__(16) __nv_bfloat16 sma[];
    const uint32_t smem_base = smem_u32(sma);

    const int tid  = threadIdx.x;
    const int lane = tid & 31;
    const int w    = tid >> 5;
    const int gid  = lane >> 2;
    const int tig  = lane & 3;
    // ldmatrix per-lane row/col offsets
    const int lrow_b = ((lane >> 4) & 1) * 8 + (lane & 7);
    const int lcol_b = ((lane >> 3) & 1) * 8;
    const int lrow_a = ((lane >> 3) & 1) * 8 + (lane & 7);
    const int lcol_a = ((lane >> 4) & 1) * 8;

    const int qt = blockIdx.x;
    const int h  = blockIdx.y;
    const int b  = blockIdx.z;
    const int bh = b * NHEAD + h;

    const __nv_bfloat16* qh_g = Qh + ((size_t)(b * SEQ + qt * 64)) * DMODEL + h * DK;
    const __nv_bfloat16* ql_g = Ql + ((size_t)(b * SEQ + qt * 64)) * DMODEL + h * DK;
    const __nv_bfloat16* kh_g = Kh + (size_t)(b * SEQ) * DMODEL + h * DK;
    const __nv_bfloat16* kl_g = Kl + (size_t)(b * SEQ) * DMODEL + h * DK;
    const __nv_bfloat16* vth_g = Vth + (size_t)bh * DK * SEQ;
    const __nv_bfloat16* vtl_g = Vtl + (size_t)bh * DK * SEQ;

    auto load_kv = [&](int kt, int st) {
        const uint32_t sb = smem_base + (uint32_t)(2 * FA_TILE_U + st * FA_STAGE_U) * 2;
#pragma unroll
        for (int it = 0; it < 16; it++) {
            const int idx = it * 128 + tid;
            const int tile = idx >> 9;
            const int within = idx & 511;
            const int row = within >> 3;
            const int ch = within & 7;
            const __nv_bfloat16* gp;
            if (tile == 0)      gp = kh_g + (size_t)(kt * 64 + row) * DMODEL + ch * 8;
            else if (tile == 1) gp = kl_g + (size_t)(kt * 64 + row) * DMODEL + ch * 8;
            else if (tile == 2) gp = vth_g + (size_t)row * SEQ + kt * 64 + ch * 8;
            else                gp = vtl_g + (size_t)row * SEQ + kt * 64 + ch * 8;
            const uint32_t da = sb + (uint32_t)(tile * FA_TILE_U + row * FA_STRIDE) * 2 + ch * 16;
            CP_ASYNC16(da, gp);
        }
    };

    // Q tiles + stage 0
#pragma unroll
    for (int it = 0; it < 8; it++) {
        const int idx = it * 128 + tid;
        const int tile = idx >> 9;
        const int within = idx & 511;
        const int row = within >> 3;
        const int ch = within & 7;
        const __nv_bfloat16* gp = (tile ? ql_g : qh_g) + (size_t)row * DMODEL + ch * 8;
        const uint32_t da = smem_base + (uint32_t)(tile * FA_TILE_U + row * FA_STRIDE) * 2 + ch * 16;
        CP_ASYNC16(da, gp);
    }
    load_kv(0, 0);
    CP_COMMIT();
    if (qt >= 1) { load_kv(1, 1); CP_COMMIT(); }

    uint32_t qa_h[4][4], qa_l[4][4];
    float oacc[8][4];
#pragma unroll
    for (int j = 0; j < 8; j++)
#pragma unroll
        for (int r = 0; r < 4; r++) oacc_init: oacc[j][r] = 0.0f;
    float mi0 = -1e30f, mi1 = -1e30f, li0 = 0.0f, li1 = 0.0f;

    for (int kt = 0; kt <= qt; kt++) {
        const int st = kt & 1;
        if (kt < qt) CP_WAIT1(); else CP_WAIT0();
        __syncthreads();

        if (kt == 0) {
#pragma unroll
            for (int kk = 0; kk < 4; kk++) {
                const uint32_t ad = smem_base +
                    (uint32_t)((16 * w + lrow_a) * FA_STRIDE + 16 * kk + lcol_a) * 2;
                LDM_X4(qa_h[kk][0], qa_h[kk][1], qa_h[kk][2], qa_h[kk][3], ad);
                LDM_X4(qa_l[kk][0], qa_l[kk][1], qa_l[kk][2], qa_l[kk][3],
                       ad + FA_TILE_U * 2);
            }
        }

        const uint32_t sbst = smem_base + (uint32_t)(2 * FA_TILE_U + st * FA_STAGE_U) * 2;

        // ---- QK^T ----
        float sS[8][4];
#pragma unroll
        for (int j = 0; j < 8; j++)
#pragma unroll
            for (int r = 0; r < 4; r++) sS[j][r] = 0.0f;

#pragma unroll
        for (int kk = 0; kk < 4; kk++) {
            uint32_t kbh[8][2], kbl[8][2];
#pragma unroll
            for (int jp = 0; jp < 4; jp++) {
                const uint32_t ad = sbst +
                    (uint32_t)((16 * jp + lrow_b) * FA_STRIDE + 16 * kk + lcol_b) * 2;
                LDM_X4(kbh[2 * jp][0], kbh[2 * jp][1], kbh[2 * jp + 1][0], kbh[2 * jp + 1][1], ad);
                LDM_X4(kbl[2 * jp][0], kbl[2 * jp][1], kbl[2 * jp + 1][0], kbl[2 * jp + 1][1],
                       ad + FA_TILE_U * 2);
            }
#pragma unroll
            for (int j = 0; j < 8; j++) {
                MMA_BF16(sS[j], qa_h[kk], kbh[j]);
                MMA_BF16(sS[j], qa_h[kk], kbl[j]);
                MMA_BF16(sS[j], qa_l[kk], kbh[j]);
            }
        }

        // ---- mask (diagonal tile) ----
        if (kt == qt) {
            const int row0 = 16 * w + gid;
            const int row1 = row0 + 8;
#pragma unroll
            for (int j = 0; j < 8; j++) {
                const int c0 = 8 * j + 2 * tig;
                if (c0 > row0)     sS[j][0] = -1e30f;
                if (c0 + 1 > row0) sS[j][1] = -1e30f;
                if (c0 > row1)     sS[j][2] = -1e30f;
                if (c0 + 1 > row1) sS[j][3] = -1e30f;
            }
        }

        // ---- online softmax ----
        float r0m = -1e30f, r1m = -1e30f;
#pragma unroll
        for (int j = 0; j < 8; j++) {
            r0m = fmaxf(r0m, fmaxf(sS[j][0], sS[j][1]));
            r1m = fmaxf(r1m, fmaxf(sS[j][2], sS[j][3]));
        }
        r0m = fmaxf(r0m, __shfl_xor_sync(0xffffffffu, r0m, 1));
        r0m = fmaxf(r0m, __shfl_xor_sync(0xffffffffu, r0m, 2));
        r1m = fmaxf(r1m, __shfl_xor_sync(0xffffffffu, r1m, 1));
        r1m = fmaxf(r1m, __shfl_xor_sync(0xffffffffu, r1m, 2));

        const float mn0 = fmaxf(mi0, r0m);
        const float mn1 = fmaxf(mi1, r1m);
        const float a0 = __expf(mi0 - mn0);
        const float a1 = __expf(mi1 - mn1);
        mi0 = mn0; mi1 = mn1;

        float sum0 = 0.0f, sum1 = 0.0f;
#pragma unroll
        for (int j = 0; j < 8; j++) {
            sS[j][0] = __expf(sS[j][0] - mn0);
            sS[j][1] = __expf(sS[j][1] - mn0);
            sS[j][2] = __expf(sS[j][2] - mn1);
            sS[j][3] = __expf(sS[j][3] - mn1);
            sum0 += sS[j][0] + sS[j][1];
            sum1 += sS[j][2] + sS[j][3];
        }
        sum0 += __shfl_xor_sync(0xffffffffu, sum0, 1);
        sum0 += __shfl_xor_sync(0xffffffffu, sum0, 2);
        sum1 += __shfl_xor_sync(0xffffffffu, sum1, 1);
        sum1 += __shfl_xor_sync(0xffffffffu, sum1, 2);
        li0 = li0 * a0 + sum0;
        li1 = li1 * a1 + sum1;

#pragma unroll
        for (int j = 0; j < 8; j++) {
            oacc[j][0] *= a0; oacc[j][1] *= a0;
            oacc[j][2] *= a1; oacc[j][3] *= a1;
        }

        // ---- PV ----
#pragma unroll
        for (int kk = 0; kk < 4; kk++) {
            uint32_t pah[4], pal[4];
            pah[0] = pack_bf16(sS[2 * kk][0], sS[2 * kk][1]);
            pah[1] = pack_bf16(sS[2 * kk][2], sS[2 * kk][3]);
            pah[2] = pack_bf16(sS[2 * kk + 1][0], sS[2 * kk + 1][1]);
            pah[3] = pack_bf16(sS[2 * kk + 1][2], sS[2 * kk + 1][3]);
            pal[0] = pack_lo(sS[2 * kk][0], sS[2 * kk][1], pah[0]);
            pal[1] = pack_lo(sS[2 * kk][2], sS[2 * kk][3], pah[1]);
            pal[2] = pack_lo(sS[2 * kk + 1][0], sS[2 * kk + 1][1], pah[2]);
            pal[3] = pack_lo(sS[2 * kk + 1][2], sS[2 * kk + 1][3], pah[3]);

            uint32_t vbh[8][2], vbl[8][2];
#pragma unroll
            for (int jp = 0; jp < 4; jp++) {
                const uint32_t ad = sbst + (uint32_t)(2 * FA_TILE_U) * 2 +
                    (uint32_t)((16 * jp + lrow_b) * FA_STRIDE + 16 * kk + lcol_b) * 2;
                LDM_X4(vbh[2 * jp][0], vbh[2 * jp][1], vbh[2 * jp + 1][0], vbh[2 * jp + 1][1], ad);
                LDM_X4(vbl[2 * jp][0], vbl[2 * jp][1], vbl[2 * jp + 1][0], vbl[2 * jp + 1][1],
                       ad + FA_TILE_U * 2);
            }
#pragma unroll
            for (int j = 0; j < 8; j++) {
                MMA_BF16(oacc[j], pah, vbh[j]);
                MMA_BF16(oacc[j], pah, vbl[j]);
                MMA_BF16(oacc[j], pal, vbh[j]);
            }
        }

        __syncthreads();
        if (kt + 2 <= qt) { load_kv(kt + 2, st); CP_COMMIT(); }
    }

    // ---- epilogue ----
    const float inv0 = 1.0f / li0;
    const float inv1 = 1.0f / li1;
    const int r0g = b * SEQ + qt * 64 + 16 * w + gid;
    float* Og = O + (size_t)r0g * DMODEL + h * DK;
#pragma unroll
    for (int j = 0; j < 8; j++) {
        const int col = 8 * j + 2 * tig;
        float2 v0 = make_float2(oacc[j][0] * inv0, oacc[j][1] * inv0);
        float2 v1 = make_float2(oacc[j][2] * inv1, oacc[j][3] * inv1);
        *(float2*)&Og[col] = v0;
        *(float2*)&Og[(size_t)8 * DMODEL + col] = v1;
    }
}

// ---------------------------------------------------------------------------
// Launch
// ---------------------------------------------------------------------------
extern "C" void kernel_launch(void* const* d_in, const int* in_sizes, int n_in,
                              void* d_out, int out_size)
{
    const float* query = (const float*)d_in[0];
    const float* key   = (const float*)d_in[1];
    const float* value = (const float*)d_in[2];
    const float* Wq = (const float*)d_in[3];
    const float* bq = (const float*)d_in[4];
    const float* Wk = (const float*)d_in[5];
    const float* bk = (const float*)d_in[6];
    const float* Wv = (const float*)d_in[7];
    const float* bv = (const float*)d_in[8];
    const float* Wo = (const float*)d_in[9];
    const float* bo = (const float*)d_in[10];
    float* out = (float*)d_out;

    float *q_s, *k_s, *v_s, *a_s;
    __nv_bfloat16 *ah, *al, *wh, *wl, *qh, *ql, *kh, *kl, *vth, *vtl;
    cudaGetSymbolAddress((void**)&q_s, g_q);
    cudaGetSymbolAddress((void**)&k_s, g_k);
    cudaGetSymbolAddress((void**)&v_s, g_v);
    cudaGetSymbolAddress((void**)&a_s, g_attn);
    cudaGetSymbolAddress((void**)&ah, g_ah);
    cudaGetSymbolAddress((void**)&al, g_al);
    cudaGetSymbolAddress((void**)&wh, g_wh);
    cudaGetSymbolAddress((void**)&wl, g_wl);
    cudaGetSymbolAddress((void**)&qh, g_qh);
    cudaGetSymbolAddress((void**)&ql, g_ql);
    cudaGetSymbolAddress((void**)&kh, g_kh);
    cudaGetSymbolAddress((void**)&kl, g_kl);
    cudaGetSymbolAddress((void**)&vth, g_vth);
    cudaGetSymbolAddress((void**)&vtl, g_vtl);

    cudaFuncSetAttribute(gemm_mma_kernel,
                         cudaFuncAttributeMaxDynamicSharedMemorySize, SMEM_GEMM_BYTES);
    cudaFuncSetAttribute(flash_mma_kernel,
                         cudaFuncAttributeMaxDynamicSharedMemorySize, FA_SMEM_BYTES);

    const dim3 gg(DMODEL / 128, MROWS / 128);
    const int nact4 = MROWS * DMODEL / 4;
    const int nw4 = DMODEL * DMODEL / 4;

    // Q projection + split (scale 1/sqrt(Dk)=0.125 folded into Q)
    cvt_split_kernel<<<nact4 / 256, 256>>>(query, ah, al, 1.0f, nact4);
    cvt_split_kernel<<<nw4 / 256, 256>>>(Wq, wh, wl, 1.0f, nw4);
    gemm_mma_kernel<<<gg, 256, SMEM_GEMM_BYTES>>>(ah, al, wh, wl, bq, q_s);
    cvt_split_kernel<<<nact4 / 256, 256>>>(q_s, qh, ql, 0.125f, nact4);
    // K projection + split
    cvt_split_kernel<<<nact4 / 256, 256>>>(key, ah, al, 1.0f, nact4);
    cvt_split_kernel<<<nw4 / 256, 256>>>(Wk, wh, wl, 1.0f, nw4);
    gemm_mma_kernel<<<gg, 256, SMEM_GEMM_BYTES>>>(ah, al, wh, wl, bk, k_s);
    cvt_split_kernel<<<nact4 / 256, 256>>>(k_s, kh, kl, 1.0f, nact4);
    // V projection + transpose-split
    cvt_split_kernel<<<nact4 / 256, 256>>>(value, ah, al, 1.0f, nact4);
    cvt_split_kernel<<<nw4 / 256, 256>>>(Wv, wh, wl, 1.0f, nw4);
    gemm_mma_kernel<<<gg, 256, SMEM_GEMM_BYTES>>>(ah, al, wh, wl, bv, v_s);
    vtrans_split_kernel<<<dim3(DMODEL / 32, MROWS / 32), dim3(32, 8)>>>(v_s, vth, vtl);

    // Attention (tensor cores)
    flash_mma_kernel<<<dim3(SEQ / 64, NHEAD, BATCH), 128, FA_SMEM_BYTES>>>(
        qh, ql, kh, kl, vth, vtl, a_s);

    // Output projection
    cvt_split_kernel<<<nact4 / 256, 256>>>(a_s, ah, al, 1.0f, nact4);
    cvt_split_kernel<<<nw4 / 256, 256>>>(Wo, wh, wl, 1.0f, nw4);
    gemm_mma_kernel<<<gg, 256, SMEM_GEMM_BYTES>>>(ah, al, wh, wl, bo, out);
}

// round 8
// speedup vs baseline: 3.3207x; 1.0358x over previous
#include <cuda_runtime.h>
#include <cuda_bf16.h>
#include <math.h>
#include <stdint.h>

#define SEQ 2048
#define DMODEL 1024
#define NHEAD 16
#define DK 64
#define BATCH 4
#define MROWS (BATCH * SEQ)   // 8192

// ---------------------------------------------------------------------------
// Scratch (device globals — no allocation allowed)
// ---------------------------------------------------------------------------
__device__ float g_v[MROWS * DMODEL];
__device__ __nv_bfloat16 g_ah[MROWS * DMODEL];
__device__ __nv_bfloat16 g_al[MROWS * DMODEL];
__device__ __nv_bfloat16 g_wh[DMODEL * DMODEL];
__device__ __nv_bfloat16 g_wl[DMODEL * DMODEL];
__device__ __nv_bfloat16 g_qh[MROWS * DMODEL];
__device__ __nv_bfloat16 g_ql[MROWS * DMODEL];
__device__ __nv_bfloat16 g_kh[MROWS * DMODEL];
__device__ __nv_bfloat16 g_kl[MROWS * DMODEL];
__device__ __nv_bfloat16 g_vth[MROWS * DMODEL];  // [bh][d][s]
__device__ __nv_bfloat16 g_vtl[MROWS * DMODEL];

// ---------------------------------------------------------------------------
// Common asm helpers
// ---------------------------------------------------------------------------
__device__ __forceinline__ uint32_t smem_u32(const void* p) {
    uint32_t a;
    asm("{ .reg .u64 t; cvta.to.shared.u64 t, %1; cvt.u32.u64 %0, t; }"
        : "=r"(a) : "l"(p));
    return a;
}
#define CP_ASYNC16(dst, src) \
    asm volatile("cp.async.cg.shared.global [%0], [%1], 16;" :: "r"(dst), "l"(src))
#define CP_COMMIT() asm volatile("cp.async.commit_group;")
#define CP_WAIT1() asm volatile("cp.async.wait_group 1;")
#define CP_WAIT0() asm volatile("cp.async.wait_group 0;")
#define MMA_BF16(c, a, b) \
    asm volatile("mma.sync.aligned.m16n8k16.row.col.f32.bf16.bf16.f32 " \
                 "{%0,%1,%2,%3}, {%4,%5,%6,%7}, {%8,%9}, {%0,%1,%2,%3};" \
                 : "+f"((c)[0]), "+f"((c)[1]), "+f"((c)[2]), "+f"((c)[3]) \
                 : "r"((a)[0]), "r"((a)[1]), "r"((a)[2]), "r"((a)[3]), \
                   "r"((b)[0]), "r"((b)[1]))
#define LDM_X4(r0, r1, r2, r3, addr) \
    asm volatile("ldmatrix.sync.aligned.m8n8.x4.shared.b16 {%0,%1,%2,%3}, [%4];" \
                 : "=r"(r0), "=r"(r1), "=r"(r2), "=r"(r3) : "r"(addr))

__device__ __forceinline__ uint32_t pack_bf16(float a, float b) {
    __nv_bfloat162 t = __floats2bfloat162_rn(a, b);
    return *(uint32_t*)&t;
}
__device__ __forceinline__ uint32_t pack_lo(float a, float b, uint32_t hpack) {
    __nv_bfloat162 h = *(__nv_bfloat162*)&hpack;
    return pack_bf16(a - __bfloat162float(h.x), b - __bfloat162float(h.y));
}

// ---------------------------------------------------------------------------
// fp32 -> (bf16 hi, bf16 lo) split kernel (2 x float4 per thread)
// ---------------------------------------------------------------------------
__global__ void cvt_split_kernel(const float* __restrict__ x,
                                 __nv_bfloat16* __restrict__ hi,
                                 __nv_bfloat16* __restrict__ lo,
                                 float sc, int n4)
{
    const int base = (blockIdx.x * blockDim.x + threadIdx.x) * 2;
#pragma unroll
    for (int u = 0; u < 2; u++) {
        const int i = base + u;
        if (i >= n4) return;
        float4 v = ((const float4*)x)[i];
        v.x *= sc; v.y *= sc; v.z *= sc; v.w *= sc;
        uint32_t hA = pack_bf16(v.x, v.y);
        uint32_t hB = pack_bf16(v.z, v.w);
        uint32_t lA = pack_lo(v.x, v.y, hA);
        uint32_t lB = pack_lo(v.z, v.w, hB);
        *(uint2*)(hi + (size_t)i * 4) = make_uint2(hA, hB);
        *(uint2*)(lo + (size_t)i * 4) = make_uint2(lA, lB);
    }
}

// ---------------------------------------------------------------------------
// V transpose + split: [b][s][h*64+d] fp32 -> [bh][d][s] bf16 hi/lo
// ---------------------------------------------------------------------------
__global__ void vtrans_split_kernel(const float* __restrict__ v,
                                    __nv_bfloat16* __restrict__ vth,
                                    __nv_bfloat16* __restrict__ vtl)
{
    __shared__ float t[32][33];
    const int c0 = blockIdx.x * 32;
    const int r0 = blockIdx.y * 32;
    const int tx = threadIdx.x, ty = threadIdx.y;
#pragma unroll
    for (int i = 0; i < 4; i++) {
        const int row = r0 + ty + i * 8;
        t[ty + i * 8][tx] = v[(size_t)row * DMODEL + c0 + tx];
    }
    __syncthreads();
#pragma unroll
    for (int i = 0; i < 4; i++) {
        const int col = c0 + ty + i * 8;
        const int srow = r0 + tx;
        const int b = srow >> 11, s = srow & 2047;
        const int h = col >> 6, d = col & 63;
        float x = t[tx][ty + i * 8];
        __nv_bfloat16 hi = __float2bfloat16(x);
        __nv_bfloat16 lo = __float2bfloat16(x - __bfloat162float(hi));
        size_t o = ((size_t)(b * NHEAD + h) * DK + d) * SEQ + s;
        vth[o] = hi;
        vtl[o] = lo;
    }
}

// ---------------------------------------------------------------------------
// mma.sync bf16 GEMM (3-term emulation): Y = X @ W^T + bias
// CTA 128x128, BK=32, 8 warps, ldmatrix fragment loads.
// Optional bf16 hi/lo output (fused split) with output scale.
// ---------------------------------------------------------------------------
#define BKC 32
#define NCHUNKS (DMODEL / BKC)
#define ROW_STRIDE 40
#define TILE_U (128 * ROW_STRIDE)
#define STAGE_U (4 * TILE_U)
#define SMEM_GEMM_BYTES (2 * STAGE_U * 2)

__global__ __launch_bounds__(256, 2)
void gemm_mma_kernel(const __nv_bfloat16* __restrict__ Ah,
                     const __nv_bfloat16* __restrict__ Al,
                     const __nv_bfloat16* __restrict__ Bh,
                     const __nv_bfloat16* __restrict__ Bl,
                     const float* __restrict__ bias,
                     float* __restrict__ Y,
                     __nv_bfloat16* __restrict__ Yh,
                     __nv_bfloat16* __restrict__ Yl,
                     float oscale)
{
    extern __shared__ __align__(16) __nv_bfloat16 smb[];
    const uint32_t smem_base = smem_u32(smb);

    const int tid  = threadIdx.x;
    const int lane = tid & 31;
    const int w    = tid >> 5;
    const int wm   = w >> 2;
    const int wn   = w & 3;
    const int gid  = lane >> 2;
    const int tig  = lane & 3;
    const int m0 = blockIdx.y * 128;
    const int n0 = blockIdx.x * 128;

    // ldmatrix lane offsets (validated in flash kernel)
    const int lrow_a = ((lane >> 3) & 1) * 8 + (lane & 7);
    const int lcol_a = ((lane >> 4) & 1) * 8;
    const int lrow_b = ((lane >> 4) & 1) * 8 + (lane & 7);
    const int lcol_b = ((lane >> 3) & 1) * 8;

    float acc[4][4][4];
#pragma unroll
    for (int i = 0; i < 4; i++)
#pragma unroll
        for (int j = 0; j < 4; j++)
#pragma unroll
            for (int r = 0; r < 4; r++) acc[i][j][r] = 0.0f;

    auto load_stage = [&](int s, int kc) {
#pragma unroll
        for (int it = 0; it < 8; it++) {
            const int tile   = it >> 1;
            const int within = (it & 1) * 256 + tid;
            const int row    = within >> 2;
            const int ch     = within & 3;
            const __nv_bfloat16* src =
                (tile == 0) ? Ah : (tile == 1) ? Al : (tile == 2) ? Bh : Bl;
            const int gbase = ((tile < 2) ? m0 : n0) + row;
            const __nv_bfloat16* gp = src + (size_t)gbase * DMODEL + kc + ch * 8;
            const uint32_t daddr = smem_base +
                (s * STAGE_U + tile * TILE_U + row * ROW_STRIDE) * 2 + ch * 16;
            CP_ASYNC16(daddr, gp);
        }
        CP_COMMIT();
    };

    load_stage(0, 0);
    load_stage(1, BKC);

    for (int c = 0; c < NCHUNKS; c++) {
        if (c < NCHUNKS - 2) CP_WAIT1(); else CP_WAIT0();
        __syncthreads();

        const uint32_t st = smem_base + (uint32_t)((c & 1) * STAGE_U) * 2;
        const uint32_t tAh = st;
        const uint32_t tAl = st + TILE_U * 2;
        const uint32_t tBh = st + 2 * TILE_U * 2;
        const uint32_t tBl = st + 3 * TILE_U * 2;

#pragma unroll
        for (int kk = 0; kk < BKC; kk += 16) {
            uint32_t ah[4][4], al[4][4], bh[4][2], bl[4][2];
#pragma unroll
            for (int i = 0; i < 4; i++) {
                const uint32_t off =
                    (uint32_t)((wm * 64 + i * 16 + lrow_a) * ROW_STRIDE + kk + lcol_a) * 2;
                LDM_X4(ah[i][0], ah[i][1], ah[i][2], ah[i][3], tAh + off);
                LDM_X4(al[i][0], al[i][1], al[i][2], al[i][3], tAl + off);
            }
#pragma unroll
            for (int jp = 0; jp < 2; jp++) {
                const uint32_t off =
                    (uint32_t)((wn * 32 + jp * 16 + lrow_b) * ROW_STRIDE + kk + lcol_b) * 2;
                LDM_X4(bh[2 * jp][0], bh[2 * jp][1], bh[2 * jp + 1][0], bh[2 * jp + 1][1],
                       tBh + off);
                LDM_X4(bl[2 * jp][0], bl[2 * jp][1], bl[2 * jp + 1][0], bl[2 * jp + 1][1],
                       tBl + off);
            }
#pragma unroll
            for (int i = 0; i < 4; i++)
#pragma unroll
                for (int j = 0; j < 4; j++) {
                    MMA_BF16(acc[i][j], ah[i], bh[j]);
                    MMA_BF16(acc[i][j], ah[i], bl[j]);
                    MMA_BF16(acc[i][j], al[i], bh[j]);
                }
        }
        __syncthreads();
        if (c + 2 < NCHUNKS) load_stage(c & 1, (c + 2) * BKC);
    }

    // ---- epilogue ----
#pragma unroll
    for (int i = 0; i < 4; i++) {
        const int r0 = m0 + wm * 64 + i * 16 + gid;
#pragma unroll
        for (int j = 0; j < 4; j++) {
            const int col = n0 + wn * 32 + j * 8 + 2 * tig;
            const float bx = bias[col];
            const float by = bias[col + 1];
            float v00 = acc[i][j][0] + bx, v01 = acc[i][j][1] + by;
            float v10 = acc[i][j][2] + bx, v11 = acc[i][j][3] + by;
            if (Yh) {
                v00 *= oscale; v01 *= oscale; v10 *= oscale; v11 *= oscale;
                uint32_t h0 = pack_bf16(v00, v01);
                uint32_t h1 = pack_bf16(v10, v11);
                uint32_t l0 = pack_lo(v00, v01, h0);
                uint32_t l1 = pack_lo(v10, v11, h1);
                *(uint32_t*)&Yh[(size_t)r0 * DMODEL + col] = h0;
                *(uint32_t*)&Yh[(size_t)(r0 + 8) * DMODEL + col] = h1;
                *(uint32_t*)&Yl[(size_t)r0 * DMODEL + col] = l0;
                *(uint32_t*)&Yl[(size_t)(r0 + 8) * DMODEL + col] = l1;
            } else {
                *(float2*)&Y[(size_t)r0 * DMODEL + col] = make_float2(v00, v01);
                *(float2*)&Y[(size_t)(r0 + 8) * DMODEL + col] = make_float2(v10, v11);
            }
        }
    }
}

// ---------------------------------------------------------------------------
// Tensor-core flash attention (causal), bf16 mma + 3-term emulation.
// Outputs bf16 hi/lo directly (fused split for the O projection).
// ---------------------------------------------------------------------------
#define FA_STRIDE 72
#define FA_TILE_U (64 * FA_STRIDE)
#define FA_STAGE_U (4 * FA_TILE_U)
#define FA_SMEM_BYTES ((2 * FA_TILE_U + 2 * FA_STAGE_U) * 2)

__global__ __launch_bounds__(128, 2)
void flash_mma_kernel(const __nv_bfloat16* __restrict__ Qh,
                      const __nv_bfloat16* __restrict__ Ql,
                      const __nv_bfloat16* __restrict__ Kh,
                      const __nv_bfloat16* __restrict__ Kl,
                      const __nv_bfloat16* __restrict__ Vth,
                      const __nv_bfloat16* __restrict__ Vtl,
                      __nv_bfloat16* __restrict__ Oh,
                      __nv_bfloat16* __restrict__ Ol)
{
    extern __shared__ __align__(16) __nv_bfloat16 sma[];
    const uint32_t smem_base = smem_u32(sma);

    const int tid  = threadIdx.x;
    const int lane = tid & 31;
    const int w    = tid >> 5;
    const int gid  = lane >> 2;
    const int tig  = lane & 3;
    const int lrow_b = ((lane >> 4) & 1) * 8 + (lane & 7);
    const int lcol_b = ((lane >> 3) & 1) * 8;
    const int lrow_a = ((lane >> 3) & 1) * 8 + (lane & 7);
    const int lcol_a = ((lane >> 4) & 1) * 8;

    const int qt = (gridDim.x - 1) - blockIdx.x;   // heavy tiles first
    const int h  = blockIdx.y;
    const int b  = blockIdx.z;
    const int bh = b * NHEAD + h;

    const __nv_bfloat16* qh_g = Qh + ((size_t)(b * SEQ + qt * 64)) * DMODEL + h * DK;
    const __nv_bfloat16* ql_g = Ql + ((size_t)(b * SEQ + qt * 64)) * DMODEL + h * DK;
    const __nv_bfloat16* kh_g = Kh + (size_t)(b * SEQ) * DMODEL + h * DK;
    const __nv_bfloat16* kl_g = Kl + (size_t)(b * SEQ) * DMODEL + h * DK;
    const __nv_bfloat16* vth_g = Vth + (size_t)bh * DK * SEQ;
    const __nv_bfloat16* vtl_g = Vtl + (size_t)bh * DK * SEQ;

    auto load_kv = [&](int kt, int st) {
        const uint32_t sb = smem_base + (uint32_t)(2 * FA_TILE_U + st * FA_STAGE_U) * 2;
#pragma unroll
        for (int it = 0; it < 16; it++) {
            const int idx = it * 128 + tid;
            const int tile = idx >> 9;
            const int within = idx & 511;
            const int row = within >> 3;
            const int ch = within & 7;
            const __nv_bfloat16* gp;
            if (tile == 0)      gp = kh_g + (size_t)(kt * 64 + row) * DMODEL + ch * 8;
            else if (tile == 1) gp = kl_g + (size_t)(kt * 64 + row) * DMODEL + ch * 8;
            else if (tile == 2) gp = vth_g + (size_t)row * SEQ + kt * 64 + ch * 8;
            else                gp = vtl_g + (size_t)row * SEQ + kt * 64 + ch * 8;
            const uint32_t da = sb + (uint32_t)(tile * FA_TILE_U + row * FA_STRIDE) * 2 + ch * 16;
            CP_ASYNC16(da, gp);
        }
    };

#pragma unroll
    for (int it = 0; it < 8; it++) {
        const int idx = it * 128 + tid;
        const int tile = idx >> 9;
        const int within = idx & 511;
        const int row = within >> 3;
        const int ch = within & 7;
        const __nv_bfloat16* gp = (tile ? ql_g : qh_g) + (size_t)row * DMODEL + ch * 8;
        const uint32_t da = smem_base + (uint32_t)(tile * FA_TILE_U + row * FA_STRIDE) * 2 + ch * 16;
        CP_ASYNC16(da, gp);
    }
    load_kv(0, 0);
    CP_COMMIT();
    if (qt >= 1) { load_kv(1, 1); CP_COMMIT(); }

    uint32_t qa_h[4][4], qa_l[4][4];
    float oacc[8][4];
#pragma unroll
    for (int j = 0; j < 8; j++)
#pragma unroll
        for (int r = 0; r < 4; r++) oacc[j][r] = 0.0f;
    float mi0 = -1e30f, mi1 = -1e30f, li0 = 0.0f, li1 = 0.0f;

    for (int kt = 0; kt <= qt; kt++) {
        const int st = kt & 1;
        if (kt < qt) CP_WAIT1(); else CP_WAIT0();
        __syncthreads();

        if (kt == 0) {
#pragma unroll
            for (int kk = 0; kk < 4; kk++) {
                const uint32_t ad = smem_base +
                    (uint32_t)((16 * w + lrow_a) * FA_STRIDE + 16 * kk + lcol_a) * 2;
                LDM_X4(qa_h[kk][0], qa_h[kk][1], qa_h[kk][2], qa_h[kk][3], ad);
                LDM_X4(qa_l[kk][0], qa_l[kk][1], qa_l[kk][2], qa_l[kk][3],
                       ad + FA_TILE_U * 2);
            }
        }

        const uint32_t sbst = smem_base + (uint32_t)(2 * FA_TILE_U + st * FA_STAGE_U) * 2;

        // ---- QK^T ----
        float sS[8][4];
#pragma unroll
        for (int j = 0; j < 8; j++)
#pragma unroll
            for (int r = 0; r < 4; r++) sS[j][r] = 0.0f;

#pragma unroll
        for (int kk = 0; kk < 4; kk++) {
            uint32_t kbh[8][2], kbl[8][2];
#pragma unroll
            for (int jp = 0; jp < 4; jp++) {
                const uint32_t ad = sbst +
                    (uint32_t)((16 * jp + lrow_b) * FA_STRIDE + 16 * kk + lcol_b) * 2;
                LDM_X4(kbh[2 * jp][0], kbh[2 * jp][1], kbh[2 * jp + 1][0], kbh[2 * jp + 1][1], ad);
                LDM_X4(kbl[2 * jp][0], kbl[2 * jp][1], kbl[2 * jp + 1][0], kbl[2 * jp + 1][1],
                       ad + FA_TILE_U * 2);
            }
#pragma unroll
            for (int j = 0; j < 8; j++) {
                MMA_BF16(sS[j], qa_h[kk], kbh[j]);
                MMA_BF16(sS[j], qa_h[kk], kbl[j]);
                MMA_BF16(sS[j], qa_l[kk], kbh[j]);
            }
        }

        if (kt == qt) {
            const int row0 = 16 * w + gid;
            const int row1 = row0 + 8;
#pragma unroll
            for (int j = 0; j < 8; j++) {
                const int c0 = 8 * j + 2 * tig;
                if (c0 > row0)     sS[j][0] = -1e30f;
                if (c0 + 1 > row0) sS[j][1] = -1e30f;
                if (c0 > row1)     sS[j][2] = -1e30f;
                if (c0 + 1 > row1) sS[j][3] = -1e30f;
            }
        }

        // ---- online softmax ----
        float r0m = -1e30f, r1m = -1e30f;
#pragma unroll
        for (int j = 0; j < 8; j++) {
            r0m = fmaxf(r0m, fmaxf(sS[j][0], sS[j][1]));
            r1m = fmaxf(r1m, fmaxf(sS[j][2], sS[j][3]));
        }
        r0m = fmaxf(r0m, __shfl_xor_sync(0xffffffffu, r0m, 1));
        r0m = fmaxf(r0m, __shfl_xor_sync(0xffffffffu, r0m, 2));
        r1m = fmaxf(r1m, __shfl_xor_sync(0xffffffffu, r1m, 1));
        r1m = fmaxf(r1m, __shfl_xor_sync(0xffffffffu, r1m, 2));

        const float mn0 = fmaxf(mi0, r0m);
        const float mn1 = fmaxf(mi1, r1m);
        const float a0 = __expf(mi0 - mn0);
        const float a1 = __expf(mi1 - mn1);
        mi0 = mn0; mi1 = mn1;

        float sum0 = 0.0f, sum1 = 0.0f;
#pragma unroll
        for (int j = 0; j < 8; j++) {
            sS[j][0] = __expf(sS[j][0] - mn0);
            sS[j][1] = __expf(sS[j][1] - mn0);
            sS[j][2] = __expf(sS[j][2] - mn1);
            sS[j][3] = __expf(sS[j][3] - mn1);
            sum0 += sS[j][0] + sS[j][1];
            sum1 += sS[j][2] + sS[j][3];
        }
        sum0 += __shfl_xor_sync(0xffffffffu, sum0, 1);
        sum0 += __shfl_xor_sync(0xffffffffu, sum0, 2);
        sum1 += __shfl_xor_sync(0xffffffffu, sum1, 1);
        sum1 += __shfl_xor_sync(0xffffffffu, sum1, 2);
        li0 = li0 * a0 + sum0;
        li1 = li1 * a1 + sum1;

#pragma unroll
        for (int j = 0; j < 8; j++) {
            oacc[j][0] *= a0; oacc[j][1] *= a0;
            oacc[j][2] *= a1; oacc[j][3] *= a1;
        }

        // ---- PV ----
#pragma unroll
        for (int kk = 0; kk < 4; kk++) {
            uint32_t pah[4], pal[4];
            pah[0] = pack_bf16(sS[2 * kk][0], sS[2 * kk][1]);
            pah[1] = pack_bf16(sS[2 * kk][2], sS[2 * kk][3]);
            pah[2] = pack_bf16(sS[2 * kk + 1][0], sS[2 * kk + 1][1]);
            pah[3] = pack_bf16(sS[2 * kk + 1][2], sS[2 * kk + 1][3]);
            pal[0] = pack_lo(sS[2 * kk][0], sS[2 * kk][1], pah[0]);
            pal[1] = pack_lo(sS[2 * kk][2], sS[2 * kk][3], pah[1]);
            pal[2] = pack_lo(sS[2 * kk + 1][0], sS[2 * kk + 1][1], pah[2]);
            pal[3] = pack_lo(sS[2 * kk + 1][2], sS[2 * kk + 1][3], pah[3]);

            uint32_t vbh[8][2], vbl[8][2];
#pragma unroll
            for (int jp = 0; jp < 4; jp++) {
                const uint32_t ad = sbst + (uint32_t)(2 * FA_TILE_U) * 2 +
                    (uint32_t)((16 * jp + lrow_b) * FA_STRIDE + 16 * kk + lcol_b) * 2;
                LDM_X4(vbh[2 * jp][0], vbh[2 * jp][1], vbh[2 * jp + 1][0], vbh[2 * jp + 1][1], ad);
                LDM_X4(vbl[2 * jp][0], vbl[2 * jp][1], vbl[2 * jp + 1][0], vbl[2 * jp + 1][1],
                       ad + FA_TILE_U * 2);
            }
#pragma unroll
            for (int j = 0; j < 8; j++) {
                MMA_BF16(oacc[j], pah, vbh[j]);
                MMA_BF16(oacc[j], pah, vbl[j]);
                MMA_BF16(oacc[j], pal, vbh[j]);
            }
        }

        __syncthreads();
        if (kt + 2 <= qt) { load_kv(kt + 2, st); CP_COMMIT(); }
    }

    // ---- epilogue: fused fp32 -> bf16 hi/lo split ----
    const float inv0 = 1.0f / li0;
    const float inv1 = 1.0f / li1;
    const int r0g = b * SEQ + qt * 64 + 16 * w + gid;
    const size_t base0 = (size_t)r0g * DMODEL + h * DK;
    const size_t base1 = base0 + (size_t)8 * DMODEL;
#pragma unroll
    for (int j = 0; j < 8; j++) {
        const int col = 8 * j + 2 * tig;
        const float v00 = oacc[j][0] * inv0, v01 = oacc[j][1] * inv0;
        const float v10 = oacc[j][2] * inv1, v11 = oacc[j][3] * inv1;
        uint32_t h0 = pack_bf16(v00, v01);
        uint32_t h1 = pack_bf16(v10, v11);
        uint32_t l0 = pack_lo(v00, v01, h0);
        uint32_t l1 = pack_lo(v10, v11, h1);
        *(uint32_t*)&Oh[base0 + col] = h0;
        *(uint32_t*)&Oh[base1 + col] = h1;
        *(uint32_t*)&Ol[base0 + col] = l0;
        *(uint32_t*)&Ol[base1 + col] = l1;
    }
}

// ---------------------------------------------------------------------------
// Launch
// ---------------------------------------------------------------------------
extern "C" void kernel_launch(void* const* d_in, const int* in_sizes, int n_in,
                              void* d_out, int out_size)
{
    const float* query = (const float*)d_in[0];
    const float* key   = (const float*)d_in[1];
    const float* value = (const float*)d_in[2];
    const float* Wq = (const float*)d_in[3];
    const float* bq = (const float*)d_in[4];
    const float* Wk = (const float*)d_in[5];
    const float* bk = (const float*)d_in[6];
    const float* Wv = (const float*)d_in[7];
    const float* bv = (const float*)d_in[8];
    const float* Wo = (const float*)d_in[9];
    const float* bo = (const float*)d_in[10];
    float* out = (float*)d_out;

    float *v_s;
    __nv_bfloat16 *ah, *al, *wh, *wl, *qh, *ql, *kh, *kl, *vth, *vtl;
    cudaGetSymbolAddress((void**)&v_s, g_v);
    cudaGetSymbolAddress((void**)&ah, g_ah);
    cudaGetSymbolAddress((void**)&al, g_al);
    cudaGetSymbolAddress((void**)&wh, g_wh);
    cudaGetSymbolAddress((void**)&wl, g_wl);
    cudaGetSymbolAddress((void**)&qh, g_qh);
    cudaGetSymbolAddress((void**)&ql, g_ql);
    cudaGetSymbolAddress((void**)&kh, g_kh);
    cudaGetSymbolAddress((void**)&kl, g_kl);
    cudaGetSymbolAddress((void**)&vth, g_vth);
    cudaGetSymbolAddress((void**)&vtl, g_vtl);

    cudaFuncSetAttribute(gemm_mma_kernel,
                         cudaFuncAttributeMaxDynamicSharedMemorySize, SMEM_GEMM_BYTES);
    cudaFuncSetAttribute(flash_mma_kernel,
                         cudaFuncAttributeMaxDynamicSharedMemorySize, FA_SMEM_BYTES);

    const dim3 gg(DMODEL / 128, MROWS / 128);
    const int nact4 = MROWS * DMODEL / 4;
    const int nw4 = DMODEL * DMODEL / 4;

    // Q projection: GEMM outputs qh/ql directly (scale 1/8 folded in)
    cvt_split_kernel<<<nact4 / 512, 256>>>(query, ah, al, 1.0f, nact4);
    cvt_split_kernel<<<nw4 / 512, 256>>>(Wq, wh, wl, 1.0f, nw4);
    gemm_mma_kernel<<<gg, 256, SMEM_GEMM_BYTES>>>(ah, al, wh, wl, bq,
                                                  nullptr, qh, ql, 0.125f);
    // K projection: GEMM outputs kh/kl directly
    cvt_split_kernel<<<nact4 / 512, 256>>>(key, ah, al, 1.0f, nact4);
    cvt_split_kernel<<<nw4 / 512, 256>>>(Wk, wh, wl, 1.0f, nw4);
    gemm_mma_kernel<<<gg, 256, SMEM_GEMM_BYTES>>>(ah, al, wh, wl, bk,
                                                  nullptr, kh, kl, 1.0f);
    // V projection (fp32) + transpose-split
    cvt_split_kernel<<<nact4 / 512, 256>>>(value, ah, al, 1.0f, nact4);
    cvt_split_kernel<<<nw4 / 512, 256>>>(Wv, wh, wl, 1.0f, nw4);
    gemm_mma_kernel<<<gg, 256, SMEM_GEMM_BYTES>>>(ah, al, wh, wl, bv,
                                                  v_s, nullptr, nullptr, 1.0f);
    vtrans_split_kernel<<<dim3(DMODEL / 32, MROWS / 32), dim3(32, 8)>>>(v_s, vth, vtl);

    // Attention: outputs ah/al (hi/lo) for the O projection
    flash_mma_kernel<<<dim3(SEQ / 64, NHEAD, BATCH), 128, FA_SMEM_BYTES>>>(
        qh, ql, kh, kl, vth, vtl, ah, al);

    // Output projection (fp32 out)
    cvt_split_kernel<<<nw4 / 512, 256>>>(Wo, wh, wl, 1.0f, nw4);
    gemm_mma_kernel<<<gg, 256, SMEM_GEMM_BYTES>>>(ah, al, wh, wl, bo,
                                                  out, nullptr, nullptr, 1.0f);
}

// round 13
// speedup vs baseline: 3.5963x; 1.0830x over previous
#include <cuda_runtime.h>
#include <cuda_bf16.h>
#include <math.h>
#include <stdint.h>

#define SEQ 2048
#define DMODEL 1024
#define NHEAD 16
#define DK 64
#define BATCH 4
#define MROWS (BATCH * SEQ)   // 8192
#define ACT_U ((size_t)MROWS * DMODEL)
#define W_U ((size_t)DMODEL * DMODEL)

// ---------------------------------------------------------------------------
// Scratch (device globals — no allocation allowed)
// ---------------------------------------------------------------------------
__device__ float g_v[ACT_U];
__device__ __nv_bfloat16 g_ah[3 * ACT_U];
__device__ __nv_bfloat16 g_al[3 * ACT_U];
__device__ __nv_bfloat16 g_wh[4 * W_U];
__device__ __nv_bfloat16 g_wl[4 * W_U];
__device__ __nv_bfloat16 g_qh[ACT_U];
__device__ __nv_bfloat16 g_ql[ACT_U];
__device__ __nv_bfloat16 g_kh[ACT_U];
__device__ __nv_bfloat16 g_kl[ACT_U];
__device__ __nv_bfloat16 g_vth[ACT_U];  // [bh][d][s]
__device__ __nv_bfloat16 g_vtl[ACT_U];

// ---------------------------------------------------------------------------
// Common asm helpers
// ---------------------------------------------------------------------------
__device__ __forceinline__ uint32_t smem_u32(const void* p) {
    uint32_t a;
    asm("{ .reg .u64 t; cvta.to.shared.u64 t, %1; cvt.u32.u64 %0, t; }"
        : "=r"(a) : "l"(p));
    return a;
}
#define CP_ASYNC16(dst, src) \
    asm volatile("cp.async.cg.shared.global [%0], [%1], 16;" :: "r"(dst), "l"(src))
#define CP_COMMIT() asm volatile("cp.async.commit_group;")
#define CP_WAIT1() asm volatile("cp.async.wait_group 1;")
#define CP_WAIT0() asm volatile("cp.async.wait_group 0;")
#define MMA_BF16(c, a, b) \
    asm volatile("mma.sync.aligned.m16n8k16.row.col.f32.bf16.bf16.f32 " \
                 "{%0,%1,%2,%3}, {%4,%5,%6,%7}, {%8,%9}, {%0,%1,%2,%3};" \
                 : "+f"((c)[0]), "+f"((c)[1]), "+f"((c)[2]), "+f"((c)[3]) \
                 : "r"((a)[0]), "r"((a)[1]), "r"((a)[2]), "r"((a)[3]), \
                   "r"((b)[0]), "r"((b)[1]))
#define LDM_X4(r0, r1, r2, r3, addr) \
    asm volatile("ldmatrix.sync.aligned.m8n8.x4.shared.b16 {%0,%1,%2,%3}, [%4];" \
                 : "=r"(r0), "=r"(r1), "=r"(r2), "=r"(r3) : "r"(addr))

__device__ __forceinline__ uint32_t pack_bf16(float a, float b) {
    __nv_bfloat162 t = __floats2bfloat162_rn(a, b);
    return *(uint32_t*)&t;
}
__device__ __forceinline__ uint32_t pack_lo(float a, float b, uint32_t hpack) {
    __nv_bfloat162 h = *(__nv_bfloat162*)&hpack;
    return pack_bf16(a - __bfloat162float(h.x), b - __bfloat162float(h.y));
}

// ---------------------------------------------------------------------------
// Batched fp32 -> (bf16 hi, bf16 lo) splits
// ---------------------------------------------------------------------------
__global__ void cvt_act_kernel(const float* __restrict__ x0,
                               const float* __restrict__ x1,
                               const float* __restrict__ x2,
                               __nv_bfloat16* __restrict__ hi,
                               __nv_bfloat16* __restrict__ lo, int n4)
{
    const int z = blockIdx.z;
    const float* x = (z == 0) ? x0 : (z == 1) ? x1 : x2;
    hi += (size_t)z * ACT_U;
    lo += (size_t)z * ACT_U;
    const int base = (blockIdx.x * blockDim.x + threadIdx.x) * 2;
#pragma unroll
    for (int u = 0; u < 2; u++) {
        const int i = base + u;
        if (i >= n4) return;
        float4 v = ((const float4*)x)[i];
        uint32_t hA = pack_bf16(v.x, v.y);
        uint32_t hB = pack_bf16(v.z, v.w);
        uint32_t lA = pack_lo(v.x, v.y, hA);
        uint32_t lB = pack_lo(v.z, v.w, hB);
        *(uint2*)(hi + (size_t)i * 4) = make_uint2(hA, hB);
        *(uint2*)(lo + (size_t)i * 4) = make_uint2(lA, lB);
    }
}

__global__ void cvt_w_kernel(const float* __restrict__ x0,
                             const float* __restrict__ x1,
                             const float* __restrict__ x2,
                             const float* __restrict__ x3,
                             __nv_bfloat16* __restrict__ hi,
                             __nv_bfloat16* __restrict__ lo, int n4)
{
    const int z = blockIdx.z;
    const float* x = (z == 0) ? x0 : (z == 1) ? x1 : (z == 2) ? x2 : x3;
    hi += (size_t)z * W_U;
    lo += (size_t)z * W_U;
    const int base = (blockIdx.x * blockDim.x + threadIdx.x) * 2;
#pragma unroll
    for (int u = 0; u < 2; u++) {
        const int i = base + u;
        if (i >= n4) return;
        float4 v = ((const float4*)x)[i];
        uint32_t hA = pack_bf16(v.x, v.y);
        uint32_t hB = pack_bf16(v.z, v.w);
        uint32_t lA = pack_lo(v.x, v.y, hA);
        uint32_t lB = pack_lo(v.z, v.w, hB);
        *(uint2*)(hi + (size_t)i * 4) = make_uint2(hA, hB);
        *(uint2*)(lo + (size_t)i * 4) = make_uint2(lA, lB);
    }
}

// ---------------------------------------------------------------------------
// V transpose + split: [b][s][h*64+d] fp32 -> [bh][d][s] bf16 hi/lo
// ---------------------------------------------------------------------------
__global__ void vtrans_split_kernel(const float* __restrict__ v,
                                    __nv_bfloat16* __restrict__ vth,
                                    __nv_bfloat16* __restrict__ vtl)
{
    __shared__ float t[32][33];
    const int c0 = blockIdx.x * 32;
    const int r0 = blockIdx.y * 32;
    const int tx = threadIdx.x, ty = threadIdx.y;
#pragma unroll
    for (int i = 0; i < 4; i++) {
        const int row = r0 + ty + i * 8;
        t[ty + i * 8][tx] = v[(size_t)row * DMODEL + c0 + tx];
    }
    __syncthreads();
#pragma unroll
    for (int i = 0; i < 4; i++) {
        const int col = c0 + ty + i * 8;
        const int srow = r0 + tx;
        const int b = srow >> 11, s = srow & 2047;
        const int h = col >> 6, d = col & 63;
        float x = t[tx][ty + i * 8];
        __nv_bfloat16 hi = __float2bfloat16(x);
        __nv_bfloat16 lo = __float2bfloat16(x - __bfloat162float(hi));
        size_t o = ((size_t)(b * NHEAD + h) * DK + d) * SEQ + s;
        vth[o] = hi;
        vtl[o] = lo;
    }
}

// ---------------------------------------------------------------------------
// mma.sync bf16 GEMM (3-term emulation): Y = X @ W^T + bias
// z-batched via per-z argument structs.
// ---------------------------------------------------------------------------
#define BKC 32
#define NCHUNKS (DMODEL / BKC)
#define ROW_STRIDE 40
#define TILE_U (128 * ROW_STRIDE)
#define STAGE_U (4 * TILE_U)
#define SMEM_GEMM_BYTES (2 * STAGE_U * 2)

struct GP {
    const __nv_bfloat16 *Ah, *Al, *Bh, *Bl;
    const float* bias;
    float* Y;
    __nv_bfloat16 *Yh, *Yl;
    float oscale;
};

__global__ __launch_bounds__(256, 2)
void gemm_mma_kernel(GP p0, GP p1, GP p2)
{
    const GP p = (blockIdx.z == 0) ? p0 : (blockIdx.z == 1) ? p1 : p2;

    extern __shared__ __align__(16) __nv_bfloat16 smb[];
    const uint32_t smem_base = smem_u32(smb);

    const int tid  = threadIdx.x;
    const int lane = tid & 31;
    const int w    = tid >> 5;
    const int wm   = w >> 2;
    const int wn   = w & 3;
    const int gid  = lane >> 2;
    const int tig  = lane & 3;
    const int m0 = blockIdx.y * 128;
    const int n0 = blockIdx.x * 128;

    const int lrow_a = ((lane >> 3) & 1) * 8 + (lane & 7);
    const int lcol_a = ((lane >> 4) & 1) * 8;
    const int lrow_b = ((lane >> 4) & 1) * 8 + (lane & 7);
    const int lcol_b = ((lane >> 3) & 1) * 8;

    float acc[4][4][4];
#pragma unroll
    for (int i = 0; i < 4; i++)
#pragma unroll
        for (int j = 0; j < 4; j++)
#pragma unroll
            for (int r = 0; r < 4; r++) acc[i][j][r] = 0.0f;

    auto load_stage = [&](int s, int kc) {
#pragma unroll
        for (int it = 0; it < 8; it++) {
            const int tile   = it >> 1;
            const int within = (it & 1) * 256 + tid;
            const int row    = within >> 2;
            const int ch     = within & 3;
            const __nv_bfloat16* src =
                (tile == 0) ? p.Ah : (tile == 1) ? p.Al : (tile == 2) ? p.Bh : p.Bl;
            const int gbase = ((tile < 2) ? m0 : n0) + row;
            const __nv_bfloat16* gp = src + (size_t)gbase * DMODEL + kc + ch * 8;
            const uint32_t daddr = smem_base +
                (s * STAGE_U + tile * TILE_U + row * ROW_STRIDE) * 2 + ch * 16;
            CP_ASYNC16(daddr, gp);
        }
        CP_COMMIT();
    };

    load_stage(0, 0);
    load_stage(1, BKC);

    for (int c = 0; c < NCHUNKS; c++) {
        if (c < NCHUNKS - 2) CP_WAIT1(); else CP_WAIT0();
        __syncthreads();

        const uint32_t st = smem_base + (uint32_t)((c & 1) * STAGE_U) * 2;
        const uint32_t tAh = st;
        const uint32_t tAl = st + TILE_U * 2;
        const uint32_t tBh = st + 2 * TILE_U * 2;
        const uint32_t tBl = st + 3 * TILE_U * 2;

#pragma unroll
        for (int kk = 0; kk < BKC; kk += 16) {
            uint32_t ah[4][4], al[4][4], bh[4][2], bl[4][2];
#pragma unroll
            for (int i = 0; i < 4; i++) {
                const uint32_t off =
                    (uint32_t)((wm * 64 + i * 16 + lrow_a) * ROW_STRIDE + kk + lcol_a) * 2;
                LDM_X4(ah[i][0], ah[i][1], ah[i][2], ah[i][3], tAh + off);
                LDM_X4(al[i][0], al[i][1], al[i][2], al[i][3], tAl + off);
            }
#pragma unroll
            for (int jp = 0; jp < 2; jp++) {
                const uint32_t off =
                    (uint32_t)((wn * 32 + jp * 16 + lrow_b) * ROW_STRIDE + kk + lcol_b) * 2;
                LDM_X4(bh[2 * jp][0], bh[2 * jp][1], bh[2 * jp + 1][0], bh[2 * jp + 1][1],
                       tBh + off);
                LDM_X4(bl[2 * jp][0], bl[2 * jp][1], bl[2 * jp + 1][0], bl[2 * jp + 1][1],
                       tBl + off);
            }
#pragma unroll
            for (int i = 0; i < 4; i++)
#pragma unroll
                for (int j = 0; j < 4; j++) {
                    MMA_BF16(acc[i][j], ah[i], bh[j]);
                    MMA_BF16(acc[i][j], ah[i], bl[j]);
                    MMA_BF16(acc[i][j], al[i], bh[j]);
                }
        }
        __syncthreads();
        if (c + 2 < NCHUNKS) load_stage(c & 1, (c + 2) * BKC);
    }

#pragma unroll
    for (int i = 0; i < 4; i++) {
        const int r0 = m0 + wm * 64 + i * 16 + gid;
#pragma unroll
        for (int j = 0; j < 4; j++) {
            const int col = n0 + wn * 32 + j * 8 + 2 * tig;
            const float bx = p.bias[col];
            const float by = p.bias[col + 1];
            float v00 = acc[i][j][0] + bx, v01 = acc[i][j][1] + by;
            float v10 = acc[i][j][2] + bx, v11 = acc[i][j][3] + by;
            if (p.Yh) {
                v00 *= p.oscale; v01 *= p.oscale; v10 *= p.oscale; v11 *= p.oscale;
                uint32_t h0 = pack_bf16(v00, v01);
                uint32_t h1 = pack_bf16(v10, v11);
                uint32_t l0 = pack_lo(v00, v01, h0);
                uint32_t l1 = pack_lo(v10, v11, h1);
                *(uint32_t*)&p.Yh[(size_t)r0 * DMODEL + col] = h0;
                *(uint32_t*)&p.Yh[(size_t)(r0 + 8) * DMODEL + col] = h1;
                *(uint32_t*)&p.Yl[(size_t)r0 * DMODEL + col] = l0;
                *(uint32_t*)&p.Yl[(size_t)(r0 + 8) * DMODEL + col] = l1;
            } else {
                *(float2*)&p.Y[(size_t)r0 * DMODEL + col] = make_float2(v00, v01);
                *(float2*)&p.Y[(size_t)(r0 + 8) * DMODEL + col] = make_float2(v10, v11);
            }
        }
    }
}

// ---------------------------------------------------------------------------
// Tensor-core flash attention (causal), bf16 mma + 3-term emulation.
// BQ=128 (256 threads, 8 warps, warp = 16 q rows), KV tiles of 64.
// Each KV stage serves 128 q rows -> half the KV traffic of BQ=64.
// ---------------------------------------------------------------------------
#define FA_STRIDE 72
#define FA_QTILE_U (128 * FA_STRIDE)            // 9216
#define FA_KVTILE_U (64 * FA_STRIDE)            // 4608
#define FA_STAGE_U (4 * FA_KVTILE_U)            // 18432
#define FA_SMEM_BYTES ((2 * FA_QTILE_U + 2 * FA_STAGE_U) * 2)  // 110592

__global__ __launch_bounds__(256, 1)
void flash_mma_kernel(const __nv_bfloat16* __restrict__ Qh,
                      const __nv_bfloat16* __restrict__ Ql,
                      const __nv_bfloat16* __restrict__ Kh,
                      const __nv_bfloat16* __restrict__ Kl,
                      const __nv_bfloat16* __restrict__ Vth,
                      const __nv_bfloat16* __restrict__ Vtl,
                      __nv_bfloat16* __restrict__ Oh,
                      __nv_bfloat16* __restrict__ Ol)
{
    extern __shared__ __align__(16) __nv_bfloat16 sma[];
    const uint32_t smem_base = smem_u32(sma);

    const int tid  = threadIdx.x;
    const int lane = tid & 31;
    const int w    = tid >> 5;        // 0..7 -> q rows 16w..16w+15
    const int gid  = lane >> 2;
    const int tig  = lane & 3;
    const int lrow_b = ((lane >> 4) & 1) * 8 + (lane & 7);
    const int lcol_b = ((lane >> 3) & 1) * 8;
    const int lrow_a = ((lane >> 3) & 1) * 8 + (lane & 7);
    const int lcol_a = ((lane >> 4) & 1) * 8;

    const int qt = (gridDim.x - 1) - blockIdx.x;   // heavy tiles first
    const int h  = blockIdx.y;
    const int b  = blockIdx.z;
    const int bh = b * NHEAD + h;
    const int ktmax = 2 * qt + 1;

    const __nv_bfloat16* qh_g = Qh + ((size_t)(b * SEQ + qt * 128)) * DMODEL + h * DK;
    const __nv_bfloat16* ql_g = Ql + ((size_t)(b * SEQ + qt * 128)) * DMODEL + h * DK;
    const __nv_bfloat16* kh_g = Kh + (size_t)(b * SEQ) * DMODEL + h * DK;
    const __nv_bfloat16* kl_g = Kl + (size_t)(b * SEQ) * DMODEL + h * DK;
    const __nv_bfloat16* vth_g = Vth + (size_t)bh * DK * SEQ;
    const __nv_bfloat16* vtl_g = Vtl + (size_t)bh * DK * SEQ;

    auto load_kv = [&](int kt, int st) {
        const uint32_t sb = smem_base + (uint32_t)(2 * FA_QTILE_U + st * FA_STAGE_U) * 2;
#pragma unroll
        for (int it = 0; it < 8; it++) {
            const int idx = it * 256 + tid;       // 0..2047
            const int tile = idx >> 9;            // 0..3
            const int within = idx & 511;
            const int row = within >> 3;          // 0..63
            const int ch = within & 7;
            const __nv_bfloat16* gp;
            if (tile == 0)      gp = kh_g + (size_t)(kt * 64 + row) * DMODEL + ch * 8;
            else if (tile == 1) gp = kl_g + (size_t)(kt * 64 + row) * DMODEL + ch * 8;
            else if (tile == 2) gp = vth_g + (size_t)row * SEQ + kt * 64 + ch * 8;
            else                gp = vtl_g + (size_t)row * SEQ + kt * 64 + ch * 8;
            const uint32_t da = sb + (uint32_t)(tile * FA_KVTILE_U + row * FA_STRIDE) * 2 + ch * 16;
            CP_ASYNC16(da, gp);
        }
    };

    // Q tiles (hi+lo, 128 rows): 2048 16B chunks / 256 threads
#pragma unroll
    for (int it = 0; it < 8; it++) {
        const int idx = it * 256 + tid;
        const int tile = idx >> 10;               // 0..1
        const int within = idx & 1023;
        const int row = within >> 3;              // 0..127
        const int ch = within & 7;
        const __nv_bfloat16* gp = (tile ? ql_g : qh_g) + (size_t)row * DMODEL + ch * 8;
        const uint32_t da = smem_base + (uint32_t)(tile * FA_QTILE_U + row * FA_STRIDE) * 2 + ch * 16;
        CP_ASYNC16(da, gp);
    }
    load_kv(0, 0);
    CP_COMMIT();
    load_kv(1, 1);   // ktmax >= 1 always
    CP_COMMIT();

    uint32_t qa_h[4][4], qa_l[4][4];
    float oacc[8][4];
#pragma unroll
    for (int j = 0; j < 8; j++)
#pragma unroll
        for (int r = 0; r < 4; r++) oacc[j][r] = 0.0f;
    float mi0 = -1e30f, mi1 = -1e30f, li0 = 0.0f, li1 = 0.0f;

    for (int kt = 0; kt <= ktmax; kt++) {
        const int st = kt & 1;
        if (kt < ktmax) CP_WAIT1(); else CP_WAIT0();
        __syncthreads();

        if (kt == 0) {
#pragma unroll
            for (int kk = 0; kk < 4; kk++) {
                const uint32_t ad = smem_base +
                    (uint32_t)((16 * w + lrow_a) * FA_STRIDE + 16 * kk + lcol_a) * 2;
                LDM_X4(qa_h[kk][0], qa_h[kk][1], qa_h[kk][2], qa_h[kk][3], ad);
                LDM_X4(qa_l[kk][0], qa_l[kk][1], qa_l[kk][2], qa_l[kk][3],
                       ad + FA_QTILE_U * 2);
            }
        }

        const uint32_t sbst = smem_base + (uint32_t)(2 * FA_QTILE_U + st * FA_STAGE_U) * 2;

        // ---- QK^T ----
        float sS[8][4];
#pragma unroll
        for (int j = 0; j < 8; j++)
#pragma unroll
            for (int r = 0; r < 4; r++) sS[j][r] = 0.0f;

#pragma unroll
        for (int kk = 0; kk < 4; kk++) {
            uint32_t kbh[8][2], kbl[8][2];
#pragma unroll
            for (int jp = 0; jp < 4; jp++) {
                const uint32_t ad = sbst +
                    (uint32_t)((16 * jp + lrow_b) * FA_STRIDE + 16 * kk + lcol_b) * 2;
                LDM_X4(kbh[2 * jp][0], kbh[2 * jp][1], kbh[2 * jp + 1][0], kbh[2 * jp + 1][1], ad);
                LDM_X4(kbl[2 * jp][0], kbl[2 * jp][1], kbl[2 * jp + 1][0], kbl[2 * jp + 1][1],
                       ad + FA_KVTILE_U * 2);
            }
#pragma unroll
            for (int j = 0; j < 8; j++) {
                MMA_BF16(sS[j], qa_h[kk], kbh[j]);
                MMA_BF16(sS[j], qa_h[kk], kbl[j]);
                MMA_BF16(sS[j], qa_l[kk], kbh[j]);
            }
        }

        // ---- causal mask (the two tiles straddling the diagonal) ----
        if (kt >= 2 * qt) {
            const int rowg0 = qt * 128 + 16 * w + gid;
            const int rowg1 = rowg0 + 8;
            const int colb = kt * 64;
#pragma unroll
            for (int j = 0; j < 8; j++) {
                const int c0 = colb + 8 * j + 2 * tig;
                if (c0 > rowg0)     sS[j][0] = -1e30f;
                if (c0 + 1 > rowg0) sS[j][1] = -1e30f;
                if (c0 > rowg1)     sS[j][2] = -1e30f;
                if (c0 + 1 > rowg1) sS[j][3] = -1e30f;
            }
        }

        // ---- online softmax ----
        float r0m = -1e30f, r1m = -1e30f;
#pragma unroll
        for (int j = 0; j < 8; j++) {
            r0m = fmaxf(r0m, fmaxf(sS[j][0], sS[j][1]));
            r1m = fmaxf(r1m, fmaxf(sS[j][2], sS[j][3]));
        }
        r0m = fmaxf(r0m, __shfl_xor_sync(0xffffffffu, r0m, 1));
        r0m = fmaxf(r0m, __shfl_xor_sync(0xffffffffu, r0m, 2));
        r1m = fmaxf(r1m, __shfl_xor_sync(0xffffffffu, r1m, 1));
        r1m = fmaxf(r1m, __shfl_xor_sync(0xffffffffu, r1m, 2));

        const float mn0 = fmaxf(mi0, r0m);
        const float mn1 = fmaxf(mi1, r1m);
        const float a0 = __expf(mi0 - mn0);
        const float a1 = __expf(mi1 - mn1);
        mi0 = mn0; mi1 = mn1;

        float sum0 = 0.0f, sum1 = 0.0f;
#pragma unroll
        for (int j = 0; j < 8; j++) {
            sS[j][0] = __expf(sS[j][0] - mn0);
            sS[j][1] = __expf(sS[j][1] - mn0);
            sS[j][2] = __expf(sS[j][2] - mn1);
            sS[j][3] = __expf(sS[j][3] - mn1);
            sum0 += sS[j][0] + sS[j][1];
            sum1 += sS[j][2] + sS[j][3];
        }
        sum0 += __shfl_xor_sync(0xffffffffu, sum0, 1);
        sum0 += __shfl_xor_sync(0xffffffffu, sum0, 2);
        sum1 += __shfl_xor_sync(0xffffffffu, sum1, 1);
        sum1 += __shfl_xor_sync(0xffffffffu, sum1, 2);
        li0 = li0 * a0 + sum0;
        li1 = li1 * a1 + sum1;

#pragma unroll
        for (int j = 0; j < 8; j++) {
            oacc[j][0] *= a0; oacc[j][1] *= a0;
            oacc[j][2] *= a1; oacc[j][3] *= a1;
        }

        // ---- PV ----
#pragma unroll
        for (int kk = 0; kk < 4; kk++) {
            uint32_t pah[4], pal[4];
            pah[0] = pack_bf16(sS[2 * kk][0], sS[2 * kk][1]);
            pah[1] = pack_bf16(sS[2 * kk][2], sS[2 * kk][3]);
            pah[2] = pack_bf16(sS[2 * kk + 1][0], sS[2 * kk + 1][1]);
            pah[3] = pack_bf16(sS[2 * kk + 1][2], sS[2 * kk + 1][3]);
            pal[0] = pack_lo(sS[2 * kk][0], sS[2 * kk][1], pah[0]);
            pal[1] = pack_lo(sS[2 * kk][2], sS[2 * kk][3], pah[1]);
            pal[2] = pack_lo(sS[2 * kk + 1][0], sS[2 * kk + 1][1], pah[2]);
            pal[3] = pack_lo(sS[2 * kk + 1][2], sS[2 * kk + 1][3], pah[3]);

            uint32_t vbh[8][2], vbl[8][2];
#pragma unroll
            for (int jp = 0; jp < 4; jp++) {
                const uint32_t ad = sbst + (uint32_t)(2 * FA_KVTILE_U) * 2 +
                    (uint32_t)((16 * jp + lrow_b) * FA_STRIDE + 16 * kk + lcol_b) * 2;
                LDM_X4(vbh[2 * jp][0], vbh[2 * jp][1], vbh[2 * jp + 1][0], vbh[2 * jp + 1][1], ad);
                LDM_X4(vbl[2 * jp][0], vbl[2 * jp][1], vbl[2 * jp + 1][0], vbl[2 * jp + 1][1],
                       ad + FA_KVTILE_U * 2);
            }
#pragma unroll
            for (int j = 0; j < 8; j++) {
                MMA_BF16(oacc[j], pah, vbh[j]);
                MMA_BF16(oacc[j], pah, vbl[j]);
                MMA_BF16(oacc[j], pal, vbh[j]);
            }
        }

        __syncthreads();
        if (kt + 2 <= ktmax) { load_kv(kt + 2, st); CP_COMMIT(); }
    }

    // ---- epilogue: fused fp32 -> bf16 hi/lo split ----
    const float inv0 = 1.0f / li0;
    const float inv1 = 1.0f / li1;
    const int r0g = b * SEQ + qt * 128 + 16 * w + gid;
    const size_t base0 = (size_t)r0g * DMODEL + h * DK;
    const size_t base1 = base0 + (size_t)8 * DMODEL;
#pragma unroll
    for (int j = 0; j < 8; j++) {
        const int col = 8 * j + 2 * tig;
        const float v00 = oacc[j][0] * inv0, v01 = oacc[j][1] * inv0;
        const float v10 = oacc[j][2] * inv1, v11 = oacc[j][3] * inv1;
        uint32_t h0 = pack_bf16(v00, v01);
        uint32_t h1 = pack_bf16(v10, v11);
        uint32_t l0 = pack_lo(v00, v01, h0);
        uint32_t l1 = pack_lo(v10, v11, h1);
        *(uint32_t*)&Oh[base0 + col] = h0;
        *(uint32_t*)&Oh[base1 + col] = h1;
        *(uint32_t*)&Ol[base0 + col] = l0;
        *(uint32_t*)&Ol[base1 + col] = l1;
    }
}

// ---------------------------------------------------------------------------
// Launch
// ---------------------------------------------------------------------------
extern "C" void kernel_launch(void* const* d_in, const int* in_sizes, int n_in,
                              void* d_out, int out_size)
{
    const float* query = (const float*)d_in[0];
    const float* key   = (const float*)d_in[1];
    const float* value = (const float*)d_in[2];
    const float* Wq = (const float*)d_in[3];
    const float* bq = (const float*)d_in[4];
    const float* Wk = (const float*)d_in[5];
    const float* bk = (const float*)d_in[6];
    const float* Wv = (const float*)d_in[7];
    const float* bv = (const float*)d_in[8];
    const float* Wo = (const float*)d_in[9];
    const float* bo = (const float*)d_in[10];
    float* out = (float*)d_out;

    float *v_s;
    __nv_bfloat16 *ah, *al, *wh, *wl, *qh, *ql, *kh, *kl, *vth, *vtl;
    cudaGetSymbolAddress((void**)&v_s, g_v);
    cudaGetSymbolAddress((void**)&ah, g_ah);
    cudaGetSymbolAddress((void**)&al, g_al);
    cudaGetSymbolAddress((void**)&wh, g_wh);
    cudaGetSymbolAddress((void**)&wl, g_wl);
    cudaGetSymbolAddress((void**)&qh, g_qh);
    cudaGetSymbolAddress((void**)&ql, g_ql);
    cudaGetSymbolAddress((void**)&kh, g_kh);
    cudaGetSymbolAddress((void**)&kl, g_kl);
    cudaGetSymbolAddress((void**)&vth, g_vth);
    cudaGetSymbolAddress((void**)&vtl, g_vtl);

    cudaFuncSetAttribute(gemm_mma_kernel,
                         cudaFuncAttributeMaxDynamicSharedMemorySize, SMEM_GEMM_BYTES);
    cudaFuncSetAttribute(flash_mma_kernel,
                         cudaFuncAttributeMaxDynamicSharedMemorySize, FA_SMEM_BYTES);

    const int nact4 = (int)(ACT_U / 4);
    const int nw4 = (int)(W_U / 4);

    // All splits: 2 launches
    cvt_act_kernel<<<dim3(nact4 / 512, 1, 3), 256>>>(query, key, value, ah, al, nact4);
    cvt_w_kernel<<<dim3(nw4 / 512, 1, 4), 256>>>(Wq, Wk, Wv, Wo, wh, wl, nw4);

    // Fused QKV projections: one launch, grid.z = 3
    GP pQ = { ah,             al,             wh,         wl,         bq,
              nullptr, qh, ql, 0.125f };
    GP pK = { ah + ACT_U,     al + ACT_U,     wh + W_U,   wl + W_U,   bk,
              nullptr, kh, kl, 1.0f };
    GP pV = { ah + 2 * ACT_U, al + 2 * ACT_U, wh + 2 * W_U, wl + 2 * W_U, bv,
              v_s, nullptr, nullptr, 1.0f };
    gemm_mma_kernel<<<dim3(DMODEL / 128, MROWS / 128, 3), 256, SMEM_GEMM_BYTES>>>(pQ, pK, pV);

    vtrans_split_kernel<<<dim3(DMODEL / 32, MROWS / 32), dim3(32, 8)>>>(v_s, vth, vtl);

    // Attention: writes hi/lo into slot 0 of g_ah/g_al for the O projection
    flash_mma_kernel<<<dim3(SEQ / 128, NHEAD, BATCH), 256, FA_SMEM_BYTES>>>(
        qh, ql, kh, kl, vth, vtl, ah, al);

    // Output projection
    GP pO = { ah, al, wh + 3 * W_U, wl + 3 * W_U, bo, out, nullptr, nullptr, 1.0f };
    gemm_mma_kernel<<<dim3(DMODEL / 128, MROWS / 128, 1), 256, SMEM_GEMM_BYTES>>>(pO, pO, pO);
}

// round 15
// speedup vs baseline: 3.6715x; 1.0209x over previous
#include <cuda_runtime.h>
#include <cuda_fp16.h>
#include <math.h>
#include <stdint.h>

#define SEQ 2048
#define DMODEL 1024
#define NHEAD 16
#define DK 64
#define BATCH 4
#define MROWS (BATCH * SEQ)   // 8192
#define ACT_U ((size_t)MROWS * DMODEL)
#define W_U ((size_t)DMODEL * DMODEL)

// ---------------------------------------------------------------------------
// Scratch (device globals — no allocation allowed)
// ---------------------------------------------------------------------------
__device__ __half g_ah[3 * ACT_U];
__device__ __half g_al[3 * ACT_U];
__device__ __half g_wh[4 * W_U];
__device__ __half g_wl[4 * W_U];
__device__ __half g_qh[ACT_U];
__device__ __half g_ql[ACT_U];
__device__ __half g_kh[ACT_U];
__device__ __half g_kl[ACT_U];
__device__ __half g_vth[ACT_U];  // [b][h][d][s]
__device__ __half g_vtl[ACT_U];

// ---------------------------------------------------------------------------
// Common asm helpers
// ---------------------------------------------------------------------------
__device__ __forceinline__ uint32_t smem_u32(const void* p) {
    uint32_t a;
    asm("{ .reg .u64 t; cvta.to.shared.u64 t, %1; cvt.u32.u64 %0, t; }"
        : "=r"(a) : "l"(p));
    return a;
}
#define CP_ASYNC16(dst, src) \
    asm volatile("cp.async.cg.shared.global [%0], [%1], 16;" :: "r"(dst), "l"(src))
#define CP_COMMIT() asm volatile("cp.async.commit_group;")
#define CP_WAIT1() asm volatile("cp.async.wait_group 1;")
#define CP_WAIT0() asm volatile("cp.async.wait_group 0;")
#define MMA_F16(c, a, b) \
    asm volatile("mma.sync.aligned.m16n8k16.row.col.f32.f16.f16.f32 " \
                 "{%0,%1,%2,%3}, {%4,%5,%6,%7}, {%8,%9}, {%0,%1,%2,%3};" \
                 : "+f"((c)[0]), "+f"((c)[1]), "+f"((c)[2]), "+f"((c)[3]) \
                 : "r"((a)[0]), "r"((a)[1]), "r"((a)[2]), "r"((a)[3]), \
                   "r"((b)[0]), "r"((b)[1]))
#define LDM_X4(r0, r1, r2, r3, addr) \
    asm volatile("ldmatrix.sync.aligned.m8n8.x4.shared.b16 {%0,%1,%2,%3}, [%4];" \
                 : "=r"(r0), "=r"(r1), "=r"(r2), "=r"(r3) : "r"(addr))

__device__ __forceinline__ uint32_t pack_f16(float a, float b) {
    __half2 t = __floats2half2_rn(a, b);
    return *(uint32_t*)&t;
}
__device__ __forceinline__ uint32_t pack_f16lo(float a, float b, uint32_t hpack) {
    __half2 h = *(__half2*)&hpack;
    return pack_f16(a - __half2float(h.x), b - __half2float(h.y));
}

// ---------------------------------------------------------------------------
// Batched fp32 -> (fp16 hi, fp16 lo) splits
// ---------------------------------------------------------------------------
__global__ void cvt_act_kernel(const float* __restrict__ x0,
                               const float* __restrict__ x1,
                               const float* __restrict__ x2,
                               __half* __restrict__ hi,
                               __half* __restrict__ lo, int n4)
{
    const int z = blockIdx.z;
    const float* x = (z == 0) ? x0 : (z == 1) ? x1 : x2;
    hi += (size_t)z * ACT_U;
    lo += (size_t)z * ACT_U;
    const int base = (blockIdx.x * blockDim.x + threadIdx.x) * 2;
#pragma unroll
    for (int u = 0; u < 2; u++) {
        const int i = base + u;
        if (i >= n4) return;
        float4 v = ((const float4*)x)[i];
        uint32_t hA = pack_f16(v.x, v.y);
        uint32_t hB = pack_f16(v.z, v.w);
        uint32_t lA = pack_f16lo(v.x, v.y, hA);
        uint32_t lB = pack_f16lo(v.z, v.w, hB);
        *(uint2*)(hi + (size_t)i * 4) = make_uint2(hA, hB);
        *(uint2*)(lo + (size_t)i * 4) = make_uint2(lA, lB);
    }
}

__global__ void cvt_w_kernel(const float* __restrict__ x0,
                             const float* __restrict__ x1,
                             const float* __restrict__ x2,
                             const float* __restrict__ x3,
                             __half* __restrict__ hi,
                             __half* __restrict__ lo, int n4)
{
    const int z = blockIdx.z;
    const float* x = (z == 0) ? x0 : (z == 1) ? x1 : (z == 2) ? x2 : x3;
    hi += (size_t)z * W_U;
    lo += (size_t)z * W_U;
    const int base = (blockIdx.x * blockDim.x + threadIdx.x) * 2;
#pragma unroll
    for (int u = 0; u < 2; u++) {
        const int i = base + u;
        if (i >= n4) return;
        float4 v = ((const float4*)x)[i];
        uint32_t hA = pack_f16(v.x, v.y);
        uint32_t hB = pack_f16(v.z, v.w);
        uint32_t lA = pack_f16lo(v.x, v.y, hA);
        uint32_t lB = pack_f16lo(v.z, v.w, hB);
        *(uint2*)(hi + (size_t)i * 4) = make_uint2(hA, hB);
        *(uint2*)(lo + (size_t)i * 4) = make_uint2(lA, lB);
    }
}

// ---------------------------------------------------------------------------
// mma.sync fp16 GEMM (emulated fp32): Y = A @ B^T + bias
// z-batched via per-z argument structs.
// vmode: A = weight (M over DMODEL), B = activation (N over MROWS),
//        bias per ROW, output written to [b][dmodel_row][s] (transposed).
// nterms: 3 = Ah*Bh + Ah*Bl + Al*Bh; 2 = drop Al*Bh (and skip Al loads).
// ---------------------------------------------------------------------------
#define BKC 32
#define NCHUNKS (DMODEL / BKC)
#define ROW_STRIDE 40
#define TILE_U (128 * ROW_STRIDE)
#define STAGE_U (4 * TILE_U)
#define SMEM_GEMM_BYTES (2 * STAGE_U * 2)

struct GP {
    const __half *Ah, *Al, *Bh, *Bl;
    const float* bias;
    float* Y;
    __half *Yh, *Yl;
    float oscale;
    int vmode;
    int nterms;
};

__global__ __launch_bounds__(256, 2)
void gemm_mma_kernel(GP p0, GP p1, GP p2)
{
    const GP p = (blockIdx.z == 0) ? p0 : (blockIdx.z == 1) ? p1 : p2;

    extern __shared__ __align__(16) __half smb[];
    const uint32_t smem_base = smem_u32(smb);

    const int tid  = threadIdx.x;
    const int lane = tid & 31;
    const int w    = tid >> 5;
    const int wm   = w >> 2;
    const int wn   = w & 3;
    const int gid  = lane >> 2;
    const int tig  = lane & 3;
    const int m0 = (p.vmode ? blockIdx.x : blockIdx.y) * 128;
    const int n0 = (p.vmode ? blockIdx.y : blockIdx.x) * 128;

    const int lrow_a = ((lane >> 3) & 1) * 8 + (lane & 7);
    const int lcol_a = ((lane >> 4) & 1) * 8;
    const int lrow_b = ((lane >> 4) & 1) * 8 + (lane & 7);
    const int lcol_b = ((lane >> 3) & 1) * 8;

    float acc[4][4][4];
#pragma unroll
    for (int i = 0; i < 4; i++)
#pragma unroll
        for (int j = 0; j < 4; j++)
#pragma unroll
            for (int r = 0; r < 4; r++) acc[i][j][r] = 0.0f;

    auto load_stage = [&](int s, int kc) {
#pragma unroll
        for (int it = 0; it < 8; it++) {
            const int tile   = it >> 1;
            if (tile == 1 && p.nterms == 2) continue;   // Al unused
            const int within = (it & 1) * 256 + tid;
            const int row    = within >> 2;
            const int ch     = within & 3;
            const __half* src =
                (tile == 0) ? p.Ah : (tile == 1) ? p.Al : (tile == 2) ? p.Bh : p.Bl;
            const int gbase = ((tile < 2) ? m0 : n0) + row;
            const __half* gp = src + (size_t)gbase * DMODEL + kc + ch * 8;
            const uint32_t daddr = smem_base +
                (s * STAGE_U + tile * TILE_U + row * ROW_STRIDE) * 2 + ch * 16;
            CP_ASYNC16(daddr, gp);
        }
        CP_COMMIT();
    };

    load_stage(0, 0);
    load_stage(1, BKC);

    for (int c = 0; c < NCHUNKS; c++) {
        if (c < NCHUNKS - 2) CP_WAIT1(); else CP_WAIT0();
        __syncthreads();

        const uint32_t st = smem_base + (uint32_t)((c & 1) * STAGE_U) * 2;
        const uint32_t tAh = st;
        const uint32_t tAl = st + TILE_U * 2;
        const uint32_t tBh = st + 2 * TILE_U * 2;
        const uint32_t tBl = st + 3 * TILE_U * 2;

#pragma unroll
        for (int kk = 0; kk < BKC; kk += 16) {
            uint32_t ah[4][4], al[4][4], bh[4][2], bl[4][2];
#pragma unroll
            for (int i = 0; i < 4; i++) {
                const uint32_t off =
                    (uint32_t)((wm * 64 + i * 16 + lrow_a) * ROW_STRIDE + kk + lcol_a) * 2;
                LDM_X4(ah[i][0], ah[i][1], ah[i][2], ah[i][3], tAh + off);
                if (p.nterms == 3)
                    LDM_X4(al[i][0], al[i][1], al[i][2], al[i][3], tAl + off);
            }
#pragma unroll
            for (int jp = 0; jp < 2; jp++) {
                const uint32_t off =
                    (uint32_t)((wn * 32 + jp * 16 + lrow_b) * ROW_STRIDE + kk + lcol_b) * 2;
                LDM_X4(bh[2 * jp][0], bh[2 * jp][1], bh[2 * jp + 1][0], bh[2 * jp + 1][1],
                       tBh + off);
                LDM_X4(bl[2 * jp][0], bl[2 * jp][1], bl[2 * jp + 1][0], bl[2 * jp + 1][1],
                       tBl + off);
            }
#pragma unroll
            for (int i = 0; i < 4; i++)
#pragma unroll
                for (int j = 0; j < 4; j++) {
                    MMA_F16(acc[i][j], ah[i], bh[j]);
                    MMA_F16(acc[i][j], ah[i], bl[j]);
                    if (p.nterms == 3) MMA_F16(acc[i][j], al[i], bh[j]);
                }
        }
        __syncthreads();
        if (c + 2 < NCHUNKS) load_stage(c & 1, (c + 2) * BKC);
    }

    // ---- epilogue ----
#pragma unroll
    for (int i = 0; i < 4; i++) {
        const int r0 = m0 + wm * 64 + i * 16 + gid;
#pragma unroll
        for (int j = 0; j < 4; j++) {
            const int col = n0 + wn * 32 + j * 8 + 2 * tig;
            if (p.vmode) {
                // bias per row; output transposed: [b][r][s], s = col & 2047
                const float b0 = p.bias[r0];
                const float b1 = p.bias[r0 + 8];
                const float v00 = acc[i][j][0] + b0, v01 = acc[i][j][1] + b0;
                const float v10 = acc[i][j][2] + b1, v11 = acc[i][j][3] + b1;
                const size_t o0 = (size_t)(col >> 11) * ((size_t)DMODEL * SEQ)
                                + (size_t)r0 * SEQ + (col & 2047);
                const size_t o1 = o0 + (size_t)8 * SEQ;
                uint32_t h0 = pack_f16(v00, v01);
                uint32_t h1 = pack_f16(v10, v11);
                uint32_t l0 = pack_f16lo(v00, v01, h0);
                uint32_t l1 = pack_f16lo(v10, v11, h1);
                *(uint32_t*)&p.Yh[o0] = h0;
                *(uint32_t*)&p.Yh[o1] = h1;
                *(uint32_t*)&p.Yl[o0] = l0;
                *(uint32_t*)&p.Yl[o1] = l1;
            } else {
                const float bx = p.bias[col];
                const float by = p.bias[col + 1];
                float v00 = acc[i][j][0] + bx, v01 = acc[i][j][1] + by;
                float v10 = acc[i][j][2] + bx, v11 = acc[i][j][3] + by;
                if (p.Yh) {
                    v00 *= p.oscale; v01 *= p.oscale; v10 *= p.oscale; v11 *= p.oscale;
                    uint32_t h0 = pack_f16(v00, v01);
                    uint32_t h1 = pack_f16(v10, v11);
                    uint32_t l0 = pack_f16lo(v00, v01, h0);
                    uint32_t l1 = pack_f16lo(v10, v11, h1);
                    *(uint32_t*)&p.Yh[(size_t)r0 * DMODEL + col] = h0;
                    *(uint32_t*)&p.Yh[(size_t)(r0 + 8) * DMODEL + col] = h1;
                    *(uint32_t*)&p.Yl[(size_t)r0 * DMODEL + col] = l0;
                    *(uint32_t*)&p.Yl[(size_t)(r0 + 8) * DMODEL + col] = l1;
                } else {
                    *(float2*)&p.Y[(size_t)r0 * DMODEL + col] = make_float2(v00, v01);
                    *(float2*)&p.Y[(size_t)(r0 + 8) * DMODEL + col] = make_float2(v10, v11);
                }
            }
        }
    }
}

// ---------------------------------------------------------------------------
// Tensor-core flash attention (causal), fp16 mma + 3-term emulation.
// BQ=128, KV tiles of 128 (one softmax per 128 kv).  256 threads / 8 warps.
// K tile: 128 s-rows x 64 d (stride 72).  Vt tile: 64 d-rows x 128 s (stride 136).
// ---------------------------------------------------------------------------
#define FA_KSTRIDE 72
#define FA_VSTRIDE 136
#define FA_QTILE_U (128 * FA_KSTRIDE)           // 9216
#define FA_KTILE_U (128 * FA_KSTRIDE)           // 9216
#define FA_VTILE_U (64 * FA_VSTRIDE)            // 8704
#define FA_STAGE_U (2 * FA_KTILE_U + 2 * FA_VTILE_U)  // 35840
#define FA_SMEM_BYTES ((2 * FA_QTILE_U + 2 * FA_STAGE_U) * 2)  // 180224

__global__ __launch_bounds__(256, 1)
void flash_mma_kernel(const __half* __restrict__ Qh,
                      const __half* __restrict__ Ql,
                      const __half* __restrict__ Kh,
                      const __half* __restrict__ Kl,
                      const __half* __restrict__ Vth,
                      const __half* __restrict__ Vtl,
                      __half* __restrict__ Oh,
                      __half* __restrict__ Ol)
{
    extern __shared__ __align__(16) __half sma[];
    const uint32_t smem_base = smem_u32(sma);

    const int tid  = threadIdx.x;
    const int lane = tid & 31;
    const int w    = tid >> 5;        // 0..7 -> q rows 16w..16w+15
    const int gid  = lane >> 2;
    const int tig  = lane & 3;
    const int lrow_b = ((lane >> 4) & 1) * 8 + (lane & 7);
    const int lcol_b = ((lane >> 3) & 1) * 8;
    const int lrow_a = ((lane >> 3) & 1) * 8 + (lane & 7);
    const int lcol_a = ((lane >> 4) & 1) * 8;

    const int qt = (gridDim.x - 1) - blockIdx.x;   // heavy tiles first
    const int h  = blockIdx.y;
    const int b  = blockIdx.z;
    const int bh = b * NHEAD + h;

    const __half* qh_g = Qh + ((size_t)(b * SEQ + qt * 128)) * DMODEL + h * DK;
    const __half* ql_g = Ql + ((size_t)(b * SEQ + qt * 128)) * DMODEL + h * DK;
    const __half* kh_g = Kh + (size_t)(b * SEQ) * DMODEL + h * DK;
    const __half* kl_g = Kl + (size_t)(b * SEQ) * DMODEL + h * DK;
    const __half* vth_g = Vth + (size_t)bh * DK * SEQ;
    const __half* vtl_g = Vtl + (size_t)bh * DK * SEQ;

    auto load_kv = [&](int kt, int st) {
        const uint32_t sb = smem_base + (uint32_t)(2 * FA_QTILE_U + st * FA_STAGE_U) * 2;
#pragma unroll
        for (int it = 0; it < 16; it++) {
            const int idx = it * 256 + tid;       // 0..4095
            const int tile = idx >> 10;           // 0..3
            const int within = idx & 1023;
            const __half* gp;
            uint32_t da;
            if (tile < 2) {                       // K tiles: 128 rows x 64 d
                const int row = within >> 3;      // 0..127
                const int ch  = within & 7;
                gp = ((tile == 0) ? kh_g : kl_g) + (size_t)(kt * 128 + row) * DMODEL + ch * 8;
                da = sb + (uint32_t)(tile * FA_KTILE_U + row * FA_KSTRIDE) * 2 + ch * 16;
            } else {                              // Vt tiles: 64 d-rows x 128 s
                const int row = within >> 4;      // 0..63
                const int ch  = within & 15;
                gp = ((tile == 2) ? vth_g : vtl_g) + (size_t)row * SEQ + kt * 128 + ch * 8;
                da = sb + (uint32_t)(2 * FA_KTILE_U + (tile - 2) * FA_VTILE_U
                                     + row * FA_VSTRIDE) * 2 + ch * 16;
            }
            CP_ASYNC16(da, gp);
        }
    };

    // Q tiles (hi+lo, 128 rows): 2048 16B chunks / 256 threads
#pragma unroll
    for (int it = 0; it < 8; it++) {
        const int idx = it * 256 + tid;
        const int tile = idx >> 10;               // 0..1
        const int within = idx & 1023;
        const int row = within >> 3;              // 0..127
        const int ch = within & 7;
        const __half* gp = (tile ? ql_g : qh_g) + (size_t)row * DMODEL + ch * 8;
        const uint32_t da = smem_base + (uint32_t)(tile * FA_QTILE_U + row * FA_KSTRIDE) * 2 + ch * 16;
        CP_ASYNC16(da, gp);
    }
    load_kv(0, 0);
    CP_COMMIT();
    if (qt >= 1) { load_kv(1, 1); CP_COMMIT(); }

    uint32_t qa_h[4][4], qa_l[4][4];
    float oacc[8][4];
#pragma unroll
    for (int j = 0; j < 8; j++)
#pragma unroll
        for (int r = 0; r < 4; r++) oacc[j][r] = 0.0f;
    float mi0 = -1e30f, mi1 = -1e30f, li0 = 0.0f, li1 = 0.0f;

    for (int kt = 0; kt <= qt; kt++) {
        const int st = kt & 1;
        if (kt < qt) CP_WAIT1(); else CP_WAIT0();
        __syncthreads();

        if (kt == 0) {
#pragma unroll
            for (int kk = 0; kk < 4; kk++) {
                const uint32_t ad = smem_base +
                    (uint32_t)((16 * w + lrow_a) * FA_KSTRIDE + 16 * kk + lcol_a) * 2;
                LDM_X4(qa_h[kk][0], qa_h[kk][1], qa_h[kk][2], qa_h[kk][3], ad);
                LDM_X4(qa_l[kk][0], qa_l[kk][1], qa_l[kk][2], qa_l[kk][3],
                       ad + FA_QTILE_U * 2);
            }
        }

        const uint32_t sbst = smem_base + (uint32_t)(2 * FA_QTILE_U + st * FA_STAGE_U) * 2;

        // ---- QK^T (n = 128 kv cols -> 16 sS tiles) ----
        float sS[16][4];
#pragma unroll
        for (int j = 0; j < 16; j++)
#pragma unroll
            for (int r = 0; r < 4; r++) sS[j][r] = 0.0f;

#pragma unroll
        for (int kk = 0; kk < 4; kk++) {
#pragma unroll
            for (int jp = 0; jp < 8; jp++) {
                uint32_t b0h[2], b1h[2], b0l[2], b1l[2];
                const uint32_t ad = sbst +
                    (uint32_t)((16 * jp + lrow_b) * FA_KSTRIDE + 16 * kk + lcol_b) * 2;
                LDM_X4(b0h[0], b0h[1], b1h[0], b1h[1], ad);
                LDM_X4(b0l[0], b0l[1], b1l[0], b1l[1], ad + FA_KTILE_U * 2);
                MMA_F16(sS[2 * jp], qa_h[kk], b0h);
                MMA_F16(sS[2 * jp], qa_h[kk], b0l);
                MMA_F16(sS[2 * jp], qa_l[kk], b0h);
                MMA_F16(sS[2 * jp + 1], qa_h[kk], b1h);
                MMA_F16(sS[2 * jp + 1], qa_h[kk], b1l);
                MMA_F16(sS[2 * jp + 1], qa_l[kk], b1h);
            }
        }

        // ---- causal mask (single diagonal tile) ----
        if (kt == qt) {
            const int row0 = 16 * w + gid;
            const int row1 = row0 + 8;
#pragma unroll
            for (int j = 0; j < 16; j++) {
                const int c0 = 8 * j + 2 * tig;
                if (c0 > row0)     sS[j][0] = -1e30f;
                if (c0 + 1 > row0) sS[j][1] = -1e30f;
                if (c0 > row1)     sS[j][2] = -1e30f;
                if (c0 + 1 > row1) sS[j][3] = -1e30f;
            }
        }

        // ---- online softmax ----
        float r0m = -1e30f, r1m = -1e30f;
#pragma unroll
        for (int j = 0; j < 16; j++) {
            r0m = fmaxf(r0m, fmaxf(sS[j][0], sS[j][1]));
            r1m = fmaxf(r1m, fmaxf(sS[j][2], sS[j][3]));
        }
        r0m = fmaxf(r0m, __shfl_xor_sync(0xffffffffu, r0m, 1));
        r0m = fmaxf(r0m, __shfl_xor_sync(0xffffffffu, r0m, 2));
        r1m = fmaxf(r1m, __shfl_xor_sync(0xffffffffu, r1m, 1));
        r1m = fmaxf(r1m, __shfl_xor_sync(0xffffffffu, r1m, 2));

        const float mn0 = fmaxf(mi0, r0m);
        const float mn1 = fmaxf(mi1, r1m);
        const float a0 = __expf(mi0 - mn0);
        const float a1 = __expf(mi1 - mn1);
        mi0 = mn0; mi1 = mn1;

        float sum0 = 0.0f, sum1 = 0.0f;
#pragma unroll
        for (int j = 0; j < 16; j++) {
            sS[j][0] = __expf(sS[j][0] - mn0);
            sS[j][1] = __expf(sS[j][1] - mn0);
            sS[j][2] = __expf(sS[j][2] - mn1);
            sS[j][3] = __expf(sS[j][3] - mn1);
            sum0 += sS[j][0] + sS[j][1];
            sum1 += sS[j][2] + sS[j][3];
        }
        sum0 += __shfl_xor_sync(0xffffffffu, sum0, 1);
        sum0 += __shfl_xor_sync(0xffffffffu, sum0, 2);
        sum1 += __shfl_xor_sync(0xffffffffu, sum1, 1);
        sum1 += __shfl_xor_sync(0xffffffffu, sum1, 2);
        li0 = li0 * a0 + sum0;
        li1 = li1 * a1 + sum1;

#pragma unroll
        for (int j = 0; j < 8; j++) {
            oacc[j][0] *= a0; oacc[j][1] *= a0;
            oacc[j][2] *= a1; oacc[j][3] *= a1;
        }

        // ---- PV (k = 128 s -> 8 chunks of 16) ----
#pragma unroll
        for (int kk = 0; kk < 8; kk++) {
            uint32_t pah[4], pal[4];
            pah[0] = pack_f16(sS[2 * kk][0], sS[2 * kk][1]);
            pah[1] = pack_f16(sS[2 * kk][2], sS[2 * kk][3]);
            pah[2] = pack_f16(sS[2 * kk + 1][0], sS[2 * kk + 1][1]);
            pah[3] = pack_f16(sS[2 * kk + 1][2], sS[2 * kk + 1][3]);
            pal[0] = pack_f16lo(sS[2 * kk][0], sS[2 * kk][1], pah[0]);
            pal[1] = pack_f16lo(sS[2 * kk][2], sS[2 * kk][3], pah[1]);
            pal[2] = pack_f16lo(sS[2 * kk + 1][0], sS[2 * kk + 1][1], pah[2]);
            pal[3] = pack_f16lo(sS[2 * kk + 1][2], sS[2 * kk + 1][3], pah[3]);

#pragma unroll
            for (int jp = 0; jp < 4; jp++) {
                uint32_t v0h[2], v1h[2], v0l[2], v1l[2];
                const uint32_t ad = sbst + (uint32_t)(2 * FA_KTILE_U) * 2 +
                    (uint32_t)((16 * jp + lrow_b) * FA_VSTRIDE + 16 * kk + lcol_b) * 2;
                LDM_X4(v0h[0], v0h[1], v1h[0], v1h[1], ad);
                LDM_X4(v0l[0], v0l[1], v1l[0], v1l[1], ad + FA_VTILE_U * 2);
                MMA_F16(oacc[2 * jp], pah, v0h);
                MMA_F16(oacc[2 * jp], pah, v0l);
                MMA_F16(oacc[2 * jp], pal, v0h);
                MMA_F16(oacc[2 * jp + 1], pah, v1h);
                MMA_F16(oacc[2 * jp + 1], pah, v1l);
                MMA_F16(oacc[2 * jp + 1], pal, v1h);
            }
        }

        __syncthreads();
        if (kt + 2 <= qt) { load_kv(kt + 2, st); CP_COMMIT(); }
    }

    // ---- epilogue: fused fp32 -> fp16 hi/lo split ----
    const float inv0 = 1.0f / li0;
    const float inv1 = 1.0f / li1;
    const int r0g = b * SEQ + qt * 128 + 16 * w + gid;
    const size_t base0 = (size_t)r0g * DMODEL + h * DK;
    const size_t base1 = base0 + (size_t)8 * DMODEL;
#pragma unroll
    for (int j = 0; j < 8; j++) {
        const int col = 8 * j + 2 * tig;
        const float v00 = oacc[j][0] * inv0, v01 = oacc[j][1] * inv0;
        const float v10 = oacc[j][2] * inv1, v11 = oacc[j][3] * inv1;
        uint32_t h0 = pack_f16(v00, v01);
        uint32_t h1 = pack_f16(v10, v11);
        uint32_t l0 = pack_f16lo(v00, v01, h0);
        uint32_t l1 = pack_f16lo(v10, v11, h1);
        *(uint32_t*)&Oh[base0 + col] = h0;
        *(uint32_t*)&Oh[base1 + col] = h1;
        *(uint32_t*)&Ol[base0 + col] = l0;
        *(uint32_t*)&Ol[base1 + col] = l1;
    }
}

// ---------------------------------------------------------------------------
// Launch
// ---------------------------------------------------------------------------
extern "C" void kernel_launch(void* const* d_in, const int* in_sizes, int n_in,
                              void* d_out, int out_size)
{
    const float* query = (const float*)d_in[0];
    const float* key   = (const float*)d_in[1];
    const float* value = (const float*)d_in[2];
    const float* Wq = (const float*)d_in[3];
    const float* bq = (const float*)d_in[4];
    const float* Wk = (const float*)d_in[5];
    const float* bk = (const float*)d_in[6];
    const float* Wv = (const float*)d_in[7];
    const float* bv = (const float*)d_in[8];
    const float* Wo = (const float*)d_in[9];
    const float* bo = (const float*)d_in[10];
    float* out = (float*)d_out;

    __half *ah, *al, *wh, *wl, *qh, *ql, *kh, *kl, *vth, *vtl;
    cudaGetSymbolAddress((void**)&ah, g_ah);
    cudaGetSymbolAddress((void**)&al, g_al);
    cudaGetSymbolAddress((void**)&wh, g_wh);
    cudaGetSymbolAddress((void**)&wl, g_wl);
    cudaGetSymbolAddress((void**)&qh, g_qh);
    cudaGetSymbolAddress((void**)&ql, g_ql);
    cudaGetSymbolAddress((void**)&kh, g_kh);
    cudaGetSymbolAddress((void**)&kl, g_kl);
    cudaGetSymbolAddress((void**)&vth, g_vth);
    cudaGetSymbolAddress((void**)&vtl, g_vtl);

    cudaFuncSetAttribute(gemm_mma_kernel,
                         cudaFuncAttributeMaxDynamicSharedMemorySize, SMEM_GEMM_BYTES);
    cudaFuncSetAttribute(flash_mma_kernel,
                         cudaFuncAttributeMaxDynamicSharedMemorySize, FA_SMEM_BYTES);

    const int nact4 = (int)(ACT_U / 4);
    const int nw4 = (int)(W_U / 4);

    cvt_act_kernel<<<dim3(nact4 / 512, 1, 3), 256>>>(query, key, value, ah, al, nact4);
    cvt_w_kernel<<<dim3(nw4 / 512, 1, 4), 256>>>(Wq, Wk, Wv, Wo, wh, wl, nw4);

    // Fused QKV projections: one launch, grid (8, 64, 3).
    // Q: 3-term, scale 0.125 folded. K: 3-term. V: transposed (A=Wv), 2-term.
    GP pQ = { ah,             al,             wh,           wl,           bq,
              nullptr, qh, ql, 0.125f, 0, 3 };
    GP pK = { ah + ACT_U,     al + ACT_U,     wh + W_U,     wl + W_U,     bk,
              nullptr, kh, kl, 1.0f, 0, 3 };
    GP pV = { wh + 2 * W_U,   wh + 2 * W_U,   ah + 2 * ACT_U, al + 2 * ACT_U, bv,
              nullptr, vth, vtl, 1.0f, 1, 2 };
    gemm_mma_kernel<<<dim3(DMODEL / 128, MROWS / 128, 3), 256, SMEM_GEMM_BYTES>>>(pQ, pK, pV);

    // Attention: writes hi/lo into slot 0 of g_ah/g_al for the O projection
    flash_mma_kernel<<<dim3(SEQ / 128, NHEAD, BATCH), 256, FA_SMEM_BYTES>>>(
        qh, ql, kh, kl, vth, vtl, ah, al);

    // Output projection (fp32 out, 3-term)
    GP pO = { ah, al, wh + 3 * W_U, wl + 3 * W_U, bo, out, nullptr, nullptr, 1.0f, 0, 3 };
    gemm_mma_kernel<<<dim3(DMODEL / 128, MROWS / 128, 1), 256, SMEM_GEMM_BYTES>>>(pO, pO, pO);
}